// round 1
// baseline (speedup 1.0000x reference)
#include <cuda_runtime.h>
#include <math.h>

#define B_  8
#define S_  1024
#define D_  768
#define H_  12
#define DH_ 64
#define FF_ 3072
#define E_  8
#define CAP_ 2048
#define T_  8192

// ---------------- scratch (device globals; no allocations allowed) ----------
__device__ float g_q[B_*H_*S_*DH_];
__device__ float g_k[B_*H_*S_*DH_];
__device__ float g_v[B_*H_*S_*DH_];
__device__ float g_scores[100663296];      // B*H*S*S
__device__ float g_ctx[T_*D_];
__device__ float g_tmp[T_*D_];
__device__ float g_att[T_*D_];
__device__ float g_h[50331648];            // E*CAP*FF
__device__ float g_ffn[T_*D_];
__device__ int   g_cnt[E_];
__device__ int   g_tokmap[E_*CAP_];
__device__ float g_gate[T_];

__device__ __forceinline__ float gelu_f(float x) {
    return 0.5f * x * (1.0f + erff(x * 0.70710678118654752f));
}

// ---------------- generic tiled SGEMM, 128x128x8, 256 threads, 8x8/thread ---
// MODE 0: q/k/v proj   C(sel) = x @ W + b, written in [B,H,S,DH] layout
// MODE 1: scores       per z=(b*H+h): q @ k^T * 0.125 + mask[b,:]
// MODE 2: ctx          per z: probs @ v, written in [B,S,H,DH] layout
// MODE 3: ctx @ Wo -> g_tmp (plain)
// MODE 4: MoE GEMM1    gather(att) @ W1[e] + b1 -> gelu -> g_h
// MODE 5: MoE GEMM2    g_h @ W2[e] + b2, *gate, scatter -> g_ffn[token]
constexpr int BM=128, BN=128, BK=8, TM=8, TN=8;

template<int MODE>
__global__ __launch_bounds__(256) void gemm_kernel(
        const float* __restrict__ Ain, const float* __restrict__ Bin,
        const float* __restrict__ bias, const float* __restrict__ mask, int sel)
{
    constexpr int Nn  = (MODE==0||MODE==3||MODE==5)?D_ : (MODE==1)?S_ : (MODE==2)?DH_ : FF_;
    constexpr int Kk  = (MODE==1)?DH_ : (MODE==2)?S_ : (MODE==5)?FF_ : D_;
    constexpr int lda = (MODE==1)?DH_ : (MODE==2)?S_ : (MODE==5)?FF_ : D_;
    constexpr int ldb = (MODE==1||MODE==2)?DH_ : (MODE==4)?FF_ : D_;

    __shared__ float As[BK][BM];
    __shared__ float Bs[BK][BN];
    __shared__ int   rIdx[BM];
    __shared__ int   s_cnt;

    const int tid   = threadIdx.x;
    const int mBase = blockIdx.y * BM;
    const int nBase = blockIdx.x * BN;
    const int z     = blockIdx.z;

    const float* A; const float* Bp;
    if      (MODE==0) { A = Ain;                               Bp = Bin; }
    else if (MODE==1) { A = g_q + (size_t)z*S_*DH_;            Bp = g_k + (size_t)z*S_*DH_; }
    else if (MODE==2) { A = g_scores + (size_t)z*S_*S_;        Bp = g_v + (size_t)z*S_*DH_; }
    else if (MODE==3) { A = g_ctx;                             Bp = Bin; }
    else if (MODE==4) { A = g_att;  Bp = Bin + (size_t)(mBase/CAP_)*D_*FF_; }
    else              { A = g_h;    Bp = Bin + (size_t)(mBase/CAP_)*FF_*D_; }

    const int eIdx = (MODE>=4) ? (mBase / CAP_) : 0;
    int cnt = 0;
    if (MODE==4 || MODE==5) {
        if (tid==0) s_cnt = g_cnt[eIdx];
        __syncthreads();
        cnt = s_cnt;
        if ((mBase % CAP_) >= cnt) return;   // whole tile beyond used capacity
    }

    if (tid < BM) {
        int m = mBase + tid;
        int r = m;
        if (MODE==4) {
            int pos = m & (CAP_-1);
            r = (pos < cnt) ? g_tokmap[eIdx*CAP_ + pos] : 0;
        }
        rIdx[tid] = r;
    }
    __syncthreads();

    const int ty = tid >> 4, tx = tid & 15;
    const int aRow = tid >> 1, aCol = (tid & 1) * 4;
    const int bRow = tid >> 5, bCol = (tid & 31) * 4;

    float acc[TM][TN];
    #pragma unroll
    for (int i=0;i<TM;i++)
        #pragma unroll
        for (int j=0;j<TN;j++) acc[i][j]=0.f;

    for (int k0 = 0; k0 < Kk; k0 += BK) {
        float4 a4 = *(const float4*)(A + (size_t)rIdx[aRow]*lda + k0 + aCol);
        As[aCol+0][aRow]=a4.x; As[aCol+1][aRow]=a4.y;
        As[aCol+2][aRow]=a4.z; As[aCol+3][aRow]=a4.w;

        if (MODE==1) {
            // B^T: Bs[k][n] = k[(nBase+n)*DH + k0+k]
            float4 b4 = *(const float4*)(Bp + (size_t)(nBase + aRow)*ldb + k0 + aCol);
            Bs[aCol+0][aRow]=b4.x; Bs[aCol+1][aRow]=b4.y;
            Bs[aCol+2][aRow]=b4.z; Bs[aCol+3][aRow]=b4.w;
        } else {
            int n = nBase + bCol;
            float4 b4 = make_float4(0.f,0.f,0.f,0.f);
            if ((Nn % BN == 0) || n < Nn)
                b4 = *(const float4*)(Bp + (size_t)(k0 + bRow)*ldb + n);
            Bs[bRow][bCol+0]=b4.x; Bs[bRow][bCol+1]=b4.y;
            Bs[bRow][bCol+2]=b4.z; Bs[bRow][bCol+3]=b4.w;
        }
        __syncthreads();

        #pragma unroll
        for (int kk=0; kk<BK; ++kk) {
            float ra[TM], rb[TN];
            #pragma unroll
            for (int i=0;i<TM;i++) ra[i] = As[kk][ty*TM+i];
            #pragma unroll
            for (int j=0;j<TN;j++) rb[j] = Bs[kk][tx*TN+j];
            #pragma unroll
            for (int i=0;i<TM;i++)
                #pragma unroll
                for (int j=0;j<TN;j++)
                    acc[i][j] = fmaf(ra[i], rb[j], acc[i][j]);
        }
        __syncthreads();
    }

    float* C;
    if      (MODE==0) C = (sel==0)?g_q:((sel==1)?g_k:g_v);
    else if (MODE==1) C = g_scores + (size_t)z*S_*S_;
    else if (MODE==2) C = g_ctx;
    else if (MODE==3) C = g_tmp;
    else if (MODE==4) C = g_h;
    else              C = g_ffn;

    #pragma unroll
    for (int i=0;i<TM;i++) {
        int m = mBase + ty*TM + i;
        #pragma unroll
        for (int j=0;j<TN;j++) {
            int n = nBase + tx*TN + j;
            if ((Nn % BN != 0) && n >= Nn) continue;
            float v = acc[i][j];
            if (MODE==0) {
                v += bias[n];
                int b = m >> 10, s = m & (S_-1), h = n >> 6, dh = n & 63;
                C[((size_t)((b*H_ + h)*S_) + s)*DH_ + dh] = v;
            } else if (MODE==1) {
                int b = z / H_;
                C[(size_t)m*S_ + n] = v*0.125f + mask[b*S_ + n];
            } else if (MODE==2) {
                int b = z / H_, h = z % H_;
                C[((size_t)(b*S_ + m)*H_ + h)*DH_ + n] = v;
            } else if (MODE==3) {
                C[(size_t)m*D_ + n] = v;
            } else if (MODE==4) {
                int pos = m & (CAP_-1);
                if (pos < cnt)
                    C[(size_t)m*FF_ + n] = gelu_f(v + bias[eIdx*FF_ + n]);
            } else {
                int pos = m & (CAP_-1);
                if (pos < cnt) {
                    int tok = g_tokmap[eIdx*CAP_ + pos];
                    C[(size_t)tok*D_ + n] = (v + bias[eIdx*D_ + n]) * g_gate[tok];
                }
            }
        }
    }
}

// ---------------- softmax over last dim of scores (rows of 1024) ------------
__global__ __launch_bounds__(256) void softmax_kernel() {
    __shared__ float red[256];
    const int tid = threadIdx.x;
    size_t base = (size_t)blockIdx.x * S_;
    float4 v = *(const float4*)(g_scores + base + tid*4);
    float mx = fmaxf(fmaxf(v.x,v.y), fmaxf(v.z,v.w));
    red[tid]=mx; __syncthreads();
    for (int s=128; s>0; s>>=1) { if (tid<s) red[tid]=fmaxf(red[tid],red[tid+s]); __syncthreads(); }
    mx = red[0]; __syncthreads();
    v.x = expf(v.x-mx); v.y = expf(v.y-mx); v.z = expf(v.z-mx); v.w = expf(v.w-mx);
    float sm = v.x+v.y+v.z+v.w;
    red[tid]=sm; __syncthreads();
    for (int s=128; s>0; s>>=1) { if (tid<s) red[tid]+=red[tid+s]; __syncthreads(); }
    float inv = 1.0f/red[0];
    v.x*=inv; v.y*=inv; v.z*=inv; v.w*=inv;
    *(float4*)(g_scores + base + tid*4) = v;
}

// ---------------- layernorm: out = LN(a + b (+ bias)) * g + beta ------------
__global__ __launch_bounds__(256) void ln_kernel(
        const float* __restrict__ a, const float* __restrict__ bsum,
        const float* __restrict__ bias,
        const float* __restrict__ g, const float* __restrict__ beta,
        float* __restrict__ out)
{
    __shared__ float red[256];
    const int t = blockIdx.x, tid = threadIdx.x;
    const float* ap = a    + (size_t)t * D_;
    const float* bp = bsum + (size_t)t * D_;
    float v[3]; float s = 0.f;
    #pragma unroll
    for (int j=0;j<3;j++) {
        int i = tid + j*256;
        float x = ap[i] + bp[i];
        if (bias) x += bias[i];
        v[j] = x; s += x;
    }
    red[tid]=s; __syncthreads();
    for (int st=128; st>0; st>>=1) { if (tid<st) red[tid]+=red[tid+st]; __syncthreads(); }
    float mu = red[0] * (1.0f/768.0f);
    __syncthreads();
    float q = 0.f;
    #pragma unroll
    for (int j=0;j<3;j++) { float d = v[j]-mu; q += d*d; }
    red[tid]=q; __syncthreads();
    for (int st=128; st>0; st>>=1) { if (tid<st) red[tid]+=red[tid+st]; __syncthreads(); }
    float inv = rsqrtf(red[0]*(1.0f/768.0f) + 1e-12f);
    #pragma unroll
    for (int j=0;j<3;j++) {
        int i = tid + j*256;
        out[(size_t)t*D_ + i] = (v[j]-mu)*inv*g[i] + beta[i];
    }
}

// ---------------- router: softmax(att@Wr+br), top-1, atomic slot ------------
__global__ __launch_bounds__(256) void router_kernel(
        const float* __restrict__ Wr, const float* __restrict__ br)
{
    int warp = (blockIdx.x * blockDim.x + threadIdx.x) >> 5;
    int lane = threadIdx.x & 31;
    if (warp >= T_) return;
    const float* xrow = g_att + (size_t)warp * D_;
    float acc[E_];
    #pragma unroll
    for (int e=0;e<E_;e++) acc[e]=0.f;
    for (int i = lane; i < D_; i += 32) {
        float x = xrow[i];
        const float* w = Wr + i*E_;
        #pragma unroll
        for (int e=0;e<E_;e++) acc[e] += x * w[e];
    }
    #pragma unroll
    for (int e=0;e<E_;e++)
        #pragma unroll
        for (int o=16;o>0;o>>=1)
            acc[e] += __shfl_xor_sync(0xffffffffu, acc[e], o);
    if (lane == 0) {
        float best = -1e30f; int be = 0;
        #pragma unroll
        for (int e=0;e<E_;e++) {
            float l = acc[e] + br[e];
            acc[e] = l;
            if (l > best) { best = l; be = e; }   // first max wins (strict >)
        }
        float sm = 0.f;
        #pragma unroll
        for (int e=0;e<E_;e++) sm += expf(acc[e] - best);
        float gate = 1.0f / sm;                    // max softmax prob
        int pos = atomicAdd(&g_cnt[be], 1);
        if (pos < CAP_) {
            g_tokmap[be*CAP_ + pos] = warp;
            g_gate[warp] = gate;
        }
        // dropped token (never happens per spec): ffn row stays zero
    }
}

__global__ void zero_small() {
    if (threadIdx.x < E_) g_cnt[threadIdx.x] = 0;
}
__global__ void zero_ffn_kernel() {
    size_t i = (size_t)blockIdx.x * blockDim.x + threadIdx.x;
    if (i < (size_t)T_*D_) g_ffn[i] = 0.f;
}

// ---------------- launch --------------------------------------------------
extern "C" void kernel_launch(void* const* d_in, const int* in_sizes, int n_in,
                              void* d_out, int out_size) {
    const float* x    = (const float*)d_in[0];
    const float* mask = (const float*)d_in[1];
    const float* Wq   = (const float*)d_in[2];
    const float* bq   = (const float*)d_in[3];
    const float* Wk   = (const float*)d_in[4];
    const float* bk   = (const float*)d_in[5];
    const float* Wv   = (const float*)d_in[6];
    const float* bv   = (const float*)d_in[7];
    const float* Wo   = (const float*)d_in[8];
    const float* bo   = (const float*)d_in[9];
    const float* ln1g = (const float*)d_in[10];
    const float* ln1b = (const float*)d_in[11];
    const float* Wr   = (const float*)d_in[12];
    const float* br   = (const float*)d_in[13];
    const float* W1   = (const float*)d_in[14];
    const float* b1   = (const float*)d_in[15];
    const float* W2   = (const float*)d_in[16];
    const float* b2   = (const float*)d_in[17];
    const float* ln2g = (const float*)d_in[18];
    const float* ln2b = (const float*)d_in[19];
    float* out = (float*)d_out;

    // scratch pointers (resolved from device symbols; host arithmetic not allowed on them)
    float *p_tmp, *p_att, *p_ffn, *p_x_dummy;
    (void)p_x_dummy;
    cudaGetSymbolAddress((void**)&p_tmp, g_tmp);
    cudaGetSymbolAddress((void**)&p_att, g_att);
    cudaGetSymbolAddress((void**)&p_ffn, g_ffn);

    zero_small<<<1, 32>>>();
    zero_ffn_kernel<<<(T_*D_ + 1023)/1024, 1024>>>();

    // QKV projections
    gemm_kernel<0><<<dim3(D_/BN, T_/BM, 1), 256>>>(x, Wq, bq, nullptr, 0);
    gemm_kernel<0><<<dim3(D_/BN, T_/BM, 1), 256>>>(x, Wk, bk, nullptr, 1);
    gemm_kernel<0><<<dim3(D_/BN, T_/BM, 1), 256>>>(x, Wv, bv, nullptr, 2);

    // scores = q @ k^T / 8 + mask ; softmax ; ctx = probs @ v
    gemm_kernel<1><<<dim3(S_/BN, S_/BM, B_*H_), 256>>>(nullptr, nullptr, nullptr, mask, 0);
    softmax_kernel<<<B_*H_*S_, 256>>>();
    gemm_kernel<2><<<dim3(1, S_/BM, B_*H_), 256>>>(nullptr, nullptr, nullptr, nullptr, 0);

    // att = LN1(x + ctx@Wo + bo)
    gemm_kernel<3><<<dim3(D_/BN, T_/BM, 1), 256>>>(nullptr, Wo, nullptr, nullptr, 0);
    ln_kernel<<<T_, 256>>>(x, p_tmp, bo, ln1g, ln1b, p_att);

    // router + MoE
    router_kernel<<<T_/8, 256>>>(Wr, br);
    gemm_kernel<4><<<dim3(FF_/BN, (E_*CAP_)/BM, 1), 256>>>(nullptr, W1, b1, nullptr, 0);
    gemm_kernel<5><<<dim3(D_/BN, (E_*CAP_)/BM, 1), 256>>>(nullptr, W2, b2, nullptr, 0);

    // out = LN2(att + ffn)
    ln_kernel<<<T_, 256>>>(p_att, p_ffn, nullptr, ln2g, ln2b, out);
}

// round 3
// speedup vs baseline: 1.3950x; 1.3950x over previous
#include <cuda_runtime.h>
#include <mma.h>
#include <cstdint>
#include <math.h>

using namespace nvcuda;

#define B_  8
#define S_  1024
#define D_  768
#define H_  12
#define DH_ 64
#define FF_ 3072
#define E_  8
#define CAP_ 2048
#define T_  8192

// ---------------- scratch (device globals) ----------------------------------
__device__ float g_q[B_*H_*S_*DH_];
__device__ float g_k[B_*H_*S_*DH_];
__device__ float g_v[B_*H_*DH_*S_];        // transposed: [z][dh][s]
__device__ float g_scores[100663296];      // B*H*S*S
__device__ float g_ctx[T_*D_];
__device__ float g_tmp[T_*D_];
__device__ float g_att[T_*D_];
__device__ float g_h[50331648];            // E*CAP*FF
__device__ float g_ffn[T_*D_];
__device__ int   g_cnt[E_];
__device__ int   g_tokmap[E_*CAP_];
__device__ float g_gate[T_];
// pre-transposed weights, [N][K] K-major
__device__ float g_WqT[D_*D_];
__device__ float g_WkT[D_*D_];
__device__ float g_WvT[D_*D_];
__device__ float g_WoT[D_*D_];
__device__ float g_W1T[E_*FF_*D_];
__device__ float g_W2T[E_*D_*FF_];

__device__ __forceinline__ float gelu_f(float x) {
    return 0.5f * x * (1.0f + erff(x * 0.70710678118654752f));
}
__device__ __forceinline__ float tf32r(float x) {
    uint32_t r;
    asm("cvt.rna.tf32.f32 %0, %1;" : "=r"(r) : "f"(x));
    return __uint_as_float(r);
}

// ---------------- wmma tf32 GEMM ---------------------------------------------
// C tile 128 x BN. A[M][KK] K-major (opt. row-gathered), B[N][KK] K-major
// (= col_major fragment with ldm=KK).
// MODE 0: QKV proj (+bias, scatter to q/k/vT per sel)
// MODE 1: scores = q@k^T * 0.125 + mask
// MODE 2: ctx = probs @ v  (B = vT)
// MODE 3: ctx @ WoT -> g_tmp
// MODE 4: gather(att) @ W1T[e] + b1 -> gelu -> g_h
// MODE 5: g_h @ W2T[e] + b2, * gate, scatter -> g_ffn
constexpr int BK  = 32;
constexpr int LDA = 40;   // padded stride (floats)

template<int MODE, int BN, int KK>
__global__ __launch_bounds__(256)
void tgemm(const float* __restrict__ Ag, const float* __restrict__ Bg,
           const float* __restrict__ bias, const float* __restrict__ mask, int sel)
{
    constexpr int NC    = KK / BK;
    constexpr int WCOLS = BN / 4;          // warp tile: 64 x WCOLS
    constexpr int MT    = 4;               // 4 m-tiles of 16
    constexpr int NT    = WCOLS / 16;      // n-tiles of 16
    constexpr int AFLOATS = 128 * LDA;
    constexpr int BFLOATS = BN  * LDA;
    constexpr int STAGEF  = AFLOATS + BFLOATS;

    extern __shared__ float sm[];
    __shared__ int rIdx[128];
    __shared__ int s_cnt;

    const int tid = threadIdx.x, wid = tid >> 5, lane = tid & 31;
    const int wr = wid >> 2, wc = wid & 3;
    const int mBase = blockIdx.y * 128, nBase = blockIdx.x * BN, z = blockIdx.z;
    const int e = (MODE >= 4) ? (mBase >> 11) : 0;

    if (MODE == 4 || MODE == 5) {
        if (tid == 0) s_cnt = g_cnt[e];
        __syncthreads();
        if ((mBase & (CAP_-1)) >= s_cnt) return;
    }

    const float* A; const float* Bp;
    if      (MODE == 0) { A = Ag;                                Bp = Bg; }
    else if (MODE == 1) { A = g_q + (size_t)z * S_ * DH_;        Bp = g_k + (size_t)z * S_ * DH_; }
    else if (MODE == 2) { A = g_scores + (size_t)z * S_ * S_;    Bp = g_v + (size_t)z * DH_ * S_; }
    else if (MODE == 3) { A = g_ctx;                             Bp = Bg; }
    else if (MODE == 4) { A = g_att;  Bp = g_W1T + (size_t)e * FF_ * D_; }
    else                { A = g_h;    Bp = g_W2T + (size_t)e * D_ * FF_; }

    if (tid < 128) {
        int m = mBase + tid, r = m;
        if (MODE == 4) {
            int pos = m & (CAP_-1);
            r = (pos < s_cnt) ? g_tokmap[e*CAP_ + pos] : 0;
        }
        rIdx[tid] = r;
    }
    __syncthreads();

    wmma::fragment<wmma::accumulator, 16, 16, 8, float> c[MT][NT];
    #pragma unroll
    for (int i = 0; i < MT; i++)
        #pragma unroll
        for (int j = 0; j < NT; j++)
            wmma::fill_fragment(c[i][j], 0.0f);

    auto load_chunk = [&](int cix, int stg) {
        const int k0 = cix * BK;
        float* aS = sm + stg * STAGEF;
        float* bS = aS + AFLOATS;
        #pragma unroll
        for (int t = 0; t < 4; t++) {
            int idx = tid + t * 256;
            int row = idx >> 3, col = (idx & 7) * 4;
            float4 v = *(const float4*)(A + (size_t)rIdx[row] * KK + k0 + col);
            v.x = tf32r(v.x); v.y = tf32r(v.y); v.z = tf32r(v.z); v.w = tf32r(v.w);
            *(float4*)(aS + row * LDA + col) = v;
        }
        #pragma unroll
        for (int t = 0; t < BN / 32; t++) {
            int idx = tid + t * 256;
            int row = idx >> 3, col = (idx & 7) * 4;
            float4 v = *(const float4*)(Bp + (size_t)(nBase + row) * KK + k0 + col);
            v.x = tf32r(v.x); v.y = tf32r(v.y); v.z = tf32r(v.z); v.w = tf32r(v.w);
            *(float4*)(bS + row * LDA + col) = v;
        }
    };

    load_chunk(0, 0);
    __syncthreads();

    for (int cix = 0; cix < NC; cix++) {
        const int stg = cix & 1;
        if (cix + 1 < NC) load_chunk(cix + 1, stg ^ 1);

        const float* aS = sm + stg * STAGEF;
        const float* bS = aS + AFLOATS;
        #pragma unroll
        for (int ks = 0; ks < BK / 8; ks++) {
            wmma::fragment<wmma::matrix_a, 16, 16, 8, wmma::precision::tf32, wmma::row_major> af[MT];
            wmma::fragment<wmma::matrix_b, 16, 16, 8, wmma::precision::tf32, wmma::col_major> bf[NT];
            #pragma unroll
            for (int mt = 0; mt < MT; mt++)
                wmma::load_matrix_sync(af[mt], aS + (wr*64 + mt*16) * LDA + ks*8, LDA);
            #pragma unroll
            for (int nt = 0; nt < NT; nt++)
                wmma::load_matrix_sync(bf[nt], bS + (wc*WCOLS + nt*16) * LDA + ks*8, LDA);
            #pragma unroll
            for (int mt = 0; mt < MT; mt++)
                #pragma unroll
                for (int nt = 0; nt < NT; nt++)
                    wmma::mma_sync(c[mt][nt], af[mt], bf[nt], c[mt][nt]);
        }
        __syncthreads();
    }

    // ---------------- epilogue: dump accum to smem scratch, fused stores ----
    float* ws = sm + wid * 64 * WCOLS;
    #pragma unroll
    for (int mt = 0; mt < MT; mt++)
        #pragma unroll
        for (int nt = 0; nt < NT; nt++)
            wmma::store_matrix_sync(ws + (mt*16) * WCOLS + nt*16, c[mt][nt],
                                    WCOLS, wmma::mem_row_major);
    __syncwarp();

    constexpr int QPR = WCOLS / 4;          // float4s per row
    #pragma unroll
    for (int it = 0; it < 64 * QPR / 32; it++) {
        int idx = it * 32 + lane;
        int row = idx / QPR, q = idx % QPR;
        float4 v = ((const float4*)ws)[idx];
        int m  = mBase + wr * 64 + row;
        int n0 = nBase + wc * WCOLS + q * 4;

        if (MODE == 0) {
            v.x += bias[n0]; v.y += bias[n0+1]; v.z += bias[n0+2]; v.w += bias[n0+3];
            int b = m >> 10, srow = m & 1023, hh = n0 >> 6, dh = n0 & 63;
            if (sel == 2) {
                size_t base = ((size_t)(b*H_ + hh) * DH_) * S_ + srow;
                g_v[base + (size_t)(dh+0)*S_] = v.x;
                g_v[base + (size_t)(dh+1)*S_] = v.y;
                g_v[base + (size_t)(dh+2)*S_] = v.z;
                g_v[base + (size_t)(dh+3)*S_] = v.w;
            } else {
                float* dst = (sel == 0) ? g_q : g_k;
                *(float4*)(dst + (((size_t)(b*H_ + hh)) * S_ + srow) * DH_ + dh) = v;
            }
        } else if (MODE == 1) {
            int b = z / H_;
            const float4 mk = *(const float4*)(mask + b * S_ + n0);
            *(float4*)(g_scores + (size_t)z*S_*S_ + (size_t)m*S_ + n0) =
                make_float4(v.x*0.125f + mk.x, v.y*0.125f + mk.y,
                            v.z*0.125f + mk.z, v.w*0.125f + mk.w);
        } else if (MODE == 2) {
            int b = z / H_, hh = z % H_;
            *(float4*)(g_ctx + ((size_t)(b*S_ + m)) * D_ + hh*DH_ + n0) = v;
        } else if (MODE == 3) {
            *(float4*)(g_tmp + (size_t)m * D_ + n0) = v;
        } else if (MODE == 4) {
            int pos = m & (CAP_-1);
            if (pos < s_cnt) {
                const float4 bb = *(const float4*)(bias + (size_t)e*FF_ + n0);
                *(float4*)(g_h + (size_t)m * FF_ + n0) =
                    make_float4(gelu_f(v.x+bb.x), gelu_f(v.y+bb.y),
                                gelu_f(v.z+bb.z), gelu_f(v.w+bb.w));
            }
        } else {
            int pos = m & (CAP_-1);
            if (pos < s_cnt) {
                int tok = g_tokmap[e*CAP_ + pos];
                float gsc = g_gate[tok];
                const float4 bb = *(const float4*)(bias + (size_t)e*D_ + n0);
                *(float4*)(g_ffn + (size_t)tok * D_ + n0) =
                    make_float4((v.x+bb.x)*gsc, (v.y+bb.y)*gsc,
                                (v.z+bb.z)*gsc, (v.w+bb.w)*gsc);
            }
        }
    }
}

// ---------------- transpose [R][C] -> [C][R], per z-batch -------------------
__global__ __launch_bounds__(256) void transpose_kernel(
        const float* __restrict__ src, float* __restrict__ dst, int R, int C)
{
    __shared__ float t[32][33];
    const float* s = src + (size_t)blockIdx.z * R * C;
    float* d = dst + (size_t)blockIdx.z * R * C;
    int r0 = blockIdx.y * 32, c0 = blockIdx.x * 32;
    int tx = threadIdx.x, ty = threadIdx.y;
    #pragma unroll
    for (int j = 0; j < 32; j += 8)
        t[ty + j][tx] = s[(size_t)(r0 + ty + j) * C + c0 + tx];
    __syncthreads();
    #pragma unroll
    for (int j = 0; j < 32; j += 8)
        d[(size_t)(c0 + ty + j) * R + r0 + tx] = t[tx][ty + j];
}

// ---------------- softmax over rows of 1024 ---------------------------------
__global__ __launch_bounds__(256) void softmax_kernel() {
    __shared__ float red[256];
    const int tid = threadIdx.x;
    size_t base = (size_t)blockIdx.x * S_;
    float4 v = *(const float4*)(g_scores + base + tid*4);
    float mx = fmaxf(fmaxf(v.x,v.y), fmaxf(v.z,v.w));
    red[tid]=mx; __syncthreads();
    for (int s=128; s>0; s>>=1) { if (tid<s) red[tid]=fmaxf(red[tid],red[tid+s]); __syncthreads(); }
    mx = red[0]; __syncthreads();
    v.x = expf(v.x-mx); v.y = expf(v.y-mx); v.z = expf(v.z-mx); v.w = expf(v.w-mx);
    float sm = v.x+v.y+v.z+v.w;
    red[tid]=sm; __syncthreads();
    for (int s=128; s>0; s>>=1) { if (tid<s) red[tid]+=red[tid+s]; __syncthreads(); }
    float inv = 1.0f/red[0];
    v.x*=inv; v.y*=inv; v.z*=inv; v.w*=inv;
    *(float4*)(g_scores + base + tid*4) = v;
}

// ---------------- layernorm --------------------------------------------------
__global__ __launch_bounds__(256) void ln_kernel(
        const float* __restrict__ a, const float* __restrict__ bsum,
        const float* __restrict__ bias,
        const float* __restrict__ g, const float* __restrict__ beta,
        float* __restrict__ out)
{
    __shared__ float red[256];
    const int t = blockIdx.x, tid = threadIdx.x;
    const float* ap = a    + (size_t)t * D_;
    const float* bp = bsum + (size_t)t * D_;
    float v[3]; float s = 0.f;
    #pragma unroll
    for (int j=0;j<3;j++) {
        int i = tid + j*256;
        float x = ap[i] + bp[i];
        if (bias) x += bias[i];
        v[j] = x; s += x;
    }
    red[tid]=s; __syncthreads();
    for (int st=128; st>0; st>>=1) { if (tid<st) red[tid]+=red[tid+st]; __syncthreads(); }
    float mu = red[0] * (1.0f/768.0f);
    __syncthreads();
    float q = 0.f;
    #pragma unroll
    for (int j=0;j<3;j++) { float d = v[j]-mu; q += d*d; }
    red[tid]=q; __syncthreads();
    for (int st=128; st>0; st>>=1) { if (tid<st) red[tid]+=red[tid+st]; __syncthreads(); }
    float inv = rsqrtf(red[0]*(1.0f/768.0f) + 1e-12f);
    #pragma unroll
    for (int j=0;j<3;j++) {
        int i = tid + j*256;
        out[(size_t)t*D_ + i] = (v[j]-mu)*inv*g[i] + beta[i];
    }
}

// ---------------- router ------------------------------------------------------
__global__ __launch_bounds__(256) void router_kernel(
        const float* __restrict__ Wr, const float* __restrict__ br)
{
    int warp = (blockIdx.x * blockDim.x + threadIdx.x) >> 5;
    int lane = threadIdx.x & 31;
    if (warp >= T_) return;
    const float* xrow = g_att + (size_t)warp * D_;
    float acc[E_];
    #pragma unroll
    for (int e=0;e<E_;e++) acc[e]=0.f;
    for (int i = lane; i < D_; i += 32) {
        float x = xrow[i];
        const float* w = Wr + i*E_;
        #pragma unroll
        for (int e=0;e<E_;e++) acc[e] += x * w[e];
    }
    #pragma unroll
    for (int e=0;e<E_;e++)
        #pragma unroll
        for (int o=16;o>0;o>>=1)
            acc[e] += __shfl_xor_sync(0xffffffffu, acc[e], o);
    if (lane == 0) {
        float best = -1e30f; int be = 0;
        #pragma unroll
        for (int e=0;e<E_;e++) {
            float l = acc[e] + br[e];
            acc[e] = l;
            if (l > best) { best = l; be = e; }
        }
        float sm = 0.f;
        #pragma unroll
        for (int e=0;e<E_;e++) sm += expf(acc[e] - best);
        float gate = 1.0f / sm;
        int pos = atomicAdd(&g_cnt[be], 1);
        if (pos < CAP_) {
            g_tokmap[be*CAP_ + pos] = warp;
            g_gate[warp] = gate;
        }
    }
}

__global__ void zero_small() {
    if (threadIdx.x < E_) g_cnt[threadIdx.x] = 0;
}
__global__ void zero_ffn_kernel() {
    size_t i = (size_t)blockIdx.x * blockDim.x + threadIdx.x;
    if (i < (size_t)T_*D_) g_ffn[i] = 0.f;
}

// ---------------- launch ------------------------------------------------------
extern "C" void kernel_launch(void* const* d_in, const int* in_sizes, int n_in,
                              void* d_out, int out_size) {
    const float* x    = (const float*)d_in[0];
    const float* mask = (const float*)d_in[1];
    const float* Wq   = (const float*)d_in[2];
    const float* bq   = (const float*)d_in[3];
    const float* Wk   = (const float*)d_in[4];
    const float* bk   = (const float*)d_in[5];
    const float* Wv   = (const float*)d_in[6];
    const float* bv   = (const float*)d_in[7];
    const float* Wo   = (const float*)d_in[8];
    const float* bo   = (const float*)d_in[9];
    const float* ln1g = (const float*)d_in[10];
    const float* ln1b = (const float*)d_in[11];
    const float* Wr   = (const float*)d_in[12];
    const float* br   = (const float*)d_in[13];
    const float* W1   = (const float*)d_in[14];
    const float* b1   = (const float*)d_in[15];
    const float* W2   = (const float*)d_in[16];
    const float* b2   = (const float*)d_in[17];
    const float* ln2g = (const float*)d_in[18];
    const float* ln2b = (const float*)d_in[19];
    float* out = (float*)d_out;

    float *pWqT, *pWkT, *pWvT, *pWoT, *pW1T, *pW2T, *p_tmp, *p_att, *p_ffn;
    cudaGetSymbolAddress((void**)&pWqT, g_WqT);
    cudaGetSymbolAddress((void**)&pWkT, g_WkT);
    cudaGetSymbolAddress((void**)&pWvT, g_WvT);
    cudaGetSymbolAddress((void**)&pWoT, g_WoT);
    cudaGetSymbolAddress((void**)&pW1T, g_W1T);
    cudaGetSymbolAddress((void**)&pW2T, g_W2T);
    cudaGetSymbolAddress((void**)&p_tmp, g_tmp);
    cudaGetSymbolAddress((void**)&p_att, g_att);
    cudaGetSymbolAddress((void**)&p_ffn, g_ffn);

    constexpr int SH128 = 2 * (128*40 + 128*40) * 4;   // 81920
    constexpr int SH64  = 2 * (128*40 + 64*40) * 4;    // 61440
    cudaFuncSetAttribute(tgemm<0,128,768>,  cudaFuncAttributeMaxDynamicSharedMemorySize, SH128);
    cudaFuncSetAttribute(tgemm<1,128,64>,   cudaFuncAttributeMaxDynamicSharedMemorySize, SH128);
    cudaFuncSetAttribute(tgemm<2,64,1024>,  cudaFuncAttributeMaxDynamicSharedMemorySize, SH64);
    cudaFuncSetAttribute(tgemm<3,128,768>,  cudaFuncAttributeMaxDynamicSharedMemorySize, SH128);
    cudaFuncSetAttribute(tgemm<4,128,768>,  cudaFuncAttributeMaxDynamicSharedMemorySize, SH128);
    cudaFuncSetAttribute(tgemm<5,128,3072>, cudaFuncAttributeMaxDynamicSharedMemorySize, SH128);

    dim3 t32x8(32, 8);
    zero_small<<<1, 32>>>();
    zero_ffn_kernel<<<(T_*D_ + 1023)/1024, 1024>>>();

    // weight transposes (into [N][K] K-major layouts)
    transpose_kernel<<<dim3(24,24,1), t32x8>>>(Wq, pWqT, D_, D_);
    transpose_kernel<<<dim3(24,24,1), t32x8>>>(Wk, pWkT, D_, D_);
    transpose_kernel<<<dim3(24,24,1), t32x8>>>(Wv, pWvT, D_, D_);
    transpose_kernel<<<dim3(24,24,1), t32x8>>>(Wo, pWoT, D_, D_);
    transpose_kernel<<<dim3(FF_/32, D_/32,  E_), t32x8>>>(W1, pW1T, D_, FF_);
    transpose_kernel<<<dim3(D_/32,  FF_/32, E_), t32x8>>>(W2, pW2T, FF_, D_);

    // QKV projections
    tgemm<0,128,768><<<dim3(6,64,1), 256, SH128>>>(x, pWqT, bq, nullptr, 0);
    tgemm<0,128,768><<<dim3(6,64,1), 256, SH128>>>(x, pWkT, bk, nullptr, 1);
    tgemm<0,128,768><<<dim3(6,64,1), 256, SH128>>>(x, pWvT, bv, nullptr, 2);

    // attention
    tgemm<1,128,64><<<dim3(8,8,B_*H_), 256, SH128>>>(nullptr, nullptr, nullptr, mask, 0);
    softmax_kernel<<<B_*H_*S_, 256>>>();
    tgemm<2,64,1024><<<dim3(1,8,B_*H_), 256, SH64>>>(nullptr, nullptr, nullptr, nullptr, 0);

    // att = LN1(x + ctx@Wo + bo)
    tgemm<3,128,768><<<dim3(6,64,1), 256, SH128>>>(nullptr, pWoT, nullptr, nullptr, 0);
    ln_kernel<<<T_, 256>>>(x, p_tmp, bo, ln1g, ln1b, p_att);

    // router + MoE
    router_kernel<<<T_/8, 256>>>(Wr, br);
    tgemm<4,128,768><<<dim3(FF_/128, (E_*CAP_)/128, 1), 256, SH128>>>(nullptr, nullptr, b1, nullptr, 0);
    tgemm<5,128,3072><<<dim3(D_/128, (E_*CAP_)/128, 1), 256, SH128>>>(nullptr, nullptr, b2, nullptr, 0);

    // out = LN2(att + ffn)
    ln_kernel<<<T_, 256>>>(p_att, p_ffn, nullptr, ln2g, ln2b, out);
}

// round 4
// speedup vs baseline: 3.8031x; 2.7262x over previous
#include <cuda_runtime.h>
#include <cstdint>
#include <math.h>

#define B_  8
#define S_  1024
#define D_  768
#define H_  12
#define DH_ 64
#define FF_ 3072
#define E_  8
#define CAP_ 2048
#define T_  8192

// ---------------- scratch (device globals) ----------------------------------
__device__ float g_q[B_*H_*S_*DH_];
__device__ float g_k[B_*H_*S_*DH_];
__device__ float g_v[B_*H_*S_*DH_];
__device__ float g_scores[100663296];      // B*H*S*S
__device__ float g_ctx[T_*D_];
__device__ float g_tmp[T_*D_];
__device__ float g_att[T_*D_];
__device__ float g_h[50331648];            // E*CAP*FF
__device__ float g_ffn[T_*D_];
__device__ int   g_cnt[E_];
__device__ int   g_tokmap[E_*CAP_];
__device__ float g_gate[T_];

__device__ __forceinline__ float gelu_f(float x) {
    return 0.5f * x * (1.0f + erff(x * 0.70710678118654752f));
}

__device__ __forceinline__ void cpa16(uint32_t dst, const void* src) {
    asm volatile("cp.async.ca.shared.global [%0], [%1], 16;" :: "r"(dst), "l"(src));
}
__device__ __forceinline__ void cpa_commit() {
    asm volatile("cp.async.commit_group;" ::: "memory");
}
__device__ __forceinline__ void cpa_wait0() {
    asm volatile("cp.async.wait_group 0;" ::: "memory");
}
__device__ __forceinline__ void cpa_wait1() {
    asm volatile("cp.async.wait_group 1;" ::: "memory");
}
__device__ __forceinline__ void mma8(float* c, const uint32_t* a, const uint32_t* b) {
    asm volatile(
        "mma.sync.aligned.m16n8k8.row.col.f32.tf32.tf32.f32 "
        "{%0,%1,%2,%3}, {%4,%5,%6,%7}, {%8,%9}, {%0,%1,%2,%3};\n"
        : "+f"(c[0]), "+f"(c[1]), "+f"(c[2]), "+f"(c[3])
        : "r"(a[0]), "r"(a[1]), "r"(a[2]), "r"(a[3]), "r"(b[0]), "r"(b[1]));
}

// ---------------- tf32 mma.sync GEMM -----------------------------------------
// C tile 128 x BN, 256 threads = 8 warps (2 x 4), warp tile 64 x (BN/4).
// A[M][KK] k-major (opt. row-gathered via rIdx).
// B: BKMAJ=1 -> B[n][k] k-major (LDBG = k-stride per n-row)
//    BKMAJ=0 -> B[k][n] n-major (LDBG = n-stride per k-row)  [natural weights / V]
// MODE 0: QKV proj (+bias, scatter to q/k/v headed layout per sel)
// MODE 1: scores = q@k^T * 0.125 + mask
// MODE 2: ctx = probs @ v
// MODE 3: ctx @ Wo -> g_tmp
// MODE 4: gather(att) @ W1[e] + b1 -> gelu -> g_h
// MODE 5: g_h @ W2[e] + b2, * gate, scatter -> g_ffn
template<int MODE, int BN, int KK, int BKMAJ, int LDBG>
__global__ __launch_bounds__(256, 2)
void tgemm(const float* __restrict__ Ag, const float* __restrict__ Bg,
           const float* __restrict__ bias, const float* __restrict__ mask, int sel)
{
    constexpr int NC     = KK / 32;
    constexpr int WCOLS  = BN / 4;
    constexpr int NT     = WCOLS / 8;
    constexpr int LDA    = 36;                 // floats
    constexpr int LDBK   = 36;                 // k-major B stride (floats)
    constexpr int LDBN   = BN + 8;             // n-major B stride (floats)
    constexpr int ABYTES = 128 * LDA * 4;
    constexpr int BBYTES = BKMAJ ? BN * LDBK * 4 : 32 * LDBN * 4;
    constexpr int STAGE  = ABYTES + BBYTES;
    constexpr int CS     = BN + 4;             // epilogue smem stride (floats)
    constexpr int BF4    = BN / 4;

    extern __shared__ char smc[];
    __shared__ int rIdx[128];
    __shared__ int s_cnt;

    const int tid = threadIdx.x, wid = tid >> 5, lane = tid & 31;
    const int wr = wid >> 2, wc = wid & 3;
    const int g = lane >> 2, t = lane & 3;
    const int mBase = blockIdx.y * 128, nBase = blockIdx.x * BN, z = blockIdx.z;
    const int e = (MODE >= 4) ? (mBase >> 11) : 0;

    if (MODE == 4 || MODE == 5) {
        if (tid == 0) s_cnt = g_cnt[e];
        __syncthreads();
        if ((mBase & (CAP_-1)) >= s_cnt) return;
    }

    const float* A; const float* Bp;
    if      (MODE == 0) { A = Ag;                                Bp = Bg; }
    else if (MODE == 1) { A = g_q + (size_t)z * S_ * DH_;        Bp = g_k + (size_t)z * S_ * DH_; }
    else if (MODE == 2) { A = g_scores + (size_t)z * S_ * S_;    Bp = g_v + (size_t)z * S_ * DH_; }
    else if (MODE == 3) { A = g_ctx;                             Bp = Bg; }
    else if (MODE == 4) { A = g_att;  Bp = Bg + (size_t)e * D_ * FF_; }
    else                { A = g_h;    Bp = Bg + (size_t)e * FF_ * D_; }

    if (tid < 128) {
        int m = mBase + tid, r = m;
        if (MODE == 4) {
            int pos = m & (CAP_-1);
            r = (pos < s_cnt) ? g_tokmap[e*CAP_ + pos] : 0;
        }
        rIdx[tid] = r;
    }
    __syncthreads();

    uint32_t sU = (uint32_t)__cvta_generic_to_shared(smc);

    auto issue = [&](int cix) {
        const int stg = cix & 1;
        const int k0 = cix * 32;
        const uint32_t aB = sU + stg * STAGE;
        #pragma unroll
        for (int i = 0; i < 4; i++) {
            int idx = tid + i * 256;
            int row = idx >> 3, c4 = idx & 7;
            cpa16(aB + row * (LDA*4) + c4 * 16,
                  A + (size_t)rIdx[row] * KK + k0 + c4 * 4);
        }
        const uint32_t bB = aB + ABYTES;
        if (BKMAJ) {
            #pragma unroll
            for (int i = 0; i < BN/32; i++) {
                int idx = tid + i * 256;
                int row = idx >> 3, c4 = idx & 7;
                cpa16(bB + row * (LDBK*4) + c4 * 16,
                      Bp + (size_t)(nBase + row) * LDBG + k0 + c4 * 4);
            }
        } else {
            #pragma unroll
            for (int i = 0; i < (32*BF4)/256; i++) {
                int idx = tid + i * 256;
                int row = idx / BF4, c4 = idx % BF4;
                cpa16(bB + row * (LDBN*4) + c4 * 16,
                      Bp + (size_t)(k0 + row) * LDBG + nBase + c4 * 4);
            }
        }
        cpa_commit();
    };

    float acc[4][NT][4];
    #pragma unroll
    for (int i = 0; i < 4; i++)
        #pragma unroll
        for (int j = 0; j < NT; j++)
            #pragma unroll
            for (int q = 0; q < 4; q++) acc[i][j][q] = 0.f;

    issue(0);
    for (int c = 0; c < NC; c++) {
        if (c + 1 < NC) { issue(c + 1); cpa_wait1(); }
        else            { cpa_wait0(); }
        __syncthreads();

        const int stg = c & 1;
        const uint32_t* aS = (const uint32_t*)(smc + stg * STAGE);
        const uint32_t* bS = (const uint32_t*)(smc + stg * STAGE + ABYTES);
        #pragma unroll
        for (int ks = 0; ks < 4; ks++) {
            uint32_t a[4][4];
            #pragma unroll
            for (int mt = 0; mt < 4; mt++) {
                int r = wr*64 + mt*16 + g;
                int cc = ks*8 + t;
                a[mt][0] = aS[r*LDA + cc];
                a[mt][1] = aS[(r+8)*LDA + cc];
                a[mt][2] = aS[r*LDA + cc + 4];
                a[mt][3] = aS[(r+8)*LDA + cc + 4];
            }
            uint32_t b[NT][2];
            #pragma unroll
            for (int nt = 0; nt < NT; nt++) {
                int n = wc*WCOLS + nt*8 + g;
                int k = ks*8 + t;
                if (BKMAJ) {
                    b[nt][0] = bS[n*LDBK + k];
                    b[nt][1] = bS[n*LDBK + k + 4];
                } else {
                    b[nt][0] = bS[k*LDBN + n];
                    b[nt][1] = bS[(k+4)*LDBN + n];
                }
            }
            #pragma unroll
            for (int mt = 0; mt < 4; mt++)
                #pragma unroll
                for (int nt = 0; nt < NT; nt++)
                    mma8(acc[mt][nt], a[mt], b[nt]);
        }
        __syncthreads();
    }

    // ---------------- epilogue: dump accums to smem, fused float4 stores ----
    float* cSf = (float*)smc;
    #pragma unroll
    for (int mt = 0; mt < 4; mt++) {
        #pragma unroll
        for (int nt = 0; nt < NT; nt++) {
            int r = wr*64 + mt*16 + g;
            int n = wc*WCOLS + nt*8 + 2*t;
            *(float2*)(cSf + r*CS + n)     = make_float2(acc[mt][nt][0], acc[mt][nt][1]);
            *(float2*)(cSf + (r+8)*CS + n) = make_float2(acc[mt][nt][2], acc[mt][nt][3]);
        }
    }
    __syncthreads();

    constexpr int IT = (128 * BF4) / 256;
    #pragma unroll
    for (int it = 0; it < IT; it++) {
        int idx = it * 256 + tid;
        int row = idx / BF4, q = idx % BF4;
        float4 v = *(const float4*)(cSf + row*CS + q*4);
        int m  = mBase + row;
        int n0 = nBase + q*4;

        if (MODE == 0) {
            v.x += bias[n0]; v.y += bias[n0+1]; v.z += bias[n0+2]; v.w += bias[n0+3];
            int b = m >> 10, srow = m & 1023, hh = n0 >> 6, dh = n0 & 63;
            float* dst = (sel == 0) ? g_q : ((sel == 1) ? g_k : g_v);
            *(float4*)(dst + (((size_t)(b*H_ + hh)) * S_ + srow) * DH_ + dh) = v;
        } else if (MODE == 1) {
            int b = z / H_;
            const float4 mk = *(const float4*)(mask + b * S_ + n0);
            *(float4*)(g_scores + (size_t)z*S_*S_ + (size_t)m*S_ + n0) =
                make_float4(v.x*0.125f + mk.x, v.y*0.125f + mk.y,
                            v.z*0.125f + mk.z, v.w*0.125f + mk.w);
        } else if (MODE == 2) {
            int b = z / H_, hh = z % H_;
            *(float4*)(g_ctx + ((size_t)(b*S_ + m)) * D_ + hh*DH_ + n0) = v;
        } else if (MODE == 3) {
            *(float4*)(g_tmp + (size_t)m * D_ + n0) = v;
        } else if (MODE == 4) {
            int pos = m & (CAP_-1);
            if (pos < s_cnt) {
                const float4 bb = *(const float4*)(bias + (size_t)e*FF_ + n0);
                *(float4*)(g_h + (size_t)m * FF_ + n0) =
                    make_float4(gelu_f(v.x+bb.x), gelu_f(v.y+bb.y),
                                gelu_f(v.z+bb.z), gelu_f(v.w+bb.w));
            }
        } else {
            int pos = m & (CAP_-1);
            if (pos < s_cnt) {
                int tok = g_tokmap[e*CAP_ + pos];
                float gsc = g_gate[tok];
                const float4 bb = *(const float4*)(bias + (size_t)e*D_ + n0);
                *(float4*)(g_ffn + (size_t)tok * D_ + n0) =
                    make_float4((v.x+bb.x)*gsc, (v.y+bb.y)*gsc,
                                (v.z+bb.z)*gsc, (v.w+bb.w)*gsc);
            }
        }
    }
}

// ---------------- softmax over rows of 1024 ---------------------------------
__global__ __launch_bounds__(256) void softmax_kernel() {
    __shared__ float red[256];
    const int tid = threadIdx.x;
    size_t base = (size_t)blockIdx.x * S_;
    float4 v = *(const float4*)(g_scores + base + tid*4);
    float mx = fmaxf(fmaxf(v.x,v.y), fmaxf(v.z,v.w));
    red[tid]=mx; __syncthreads();
    for (int s=128; s>0; s>>=1) { if (tid<s) red[tid]=fmaxf(red[tid],red[tid+s]); __syncthreads(); }
    mx = red[0]; __syncthreads();
    v.x = expf(v.x-mx); v.y = expf(v.y-mx); v.z = expf(v.z-mx); v.w = expf(v.w-mx);
    float sm = v.x+v.y+v.z+v.w;
    red[tid]=sm; __syncthreads();
    for (int s=128; s>0; s>>=1) { if (tid<s) red[tid]+=red[tid+s]; __syncthreads(); }
    float inv = 1.0f/red[0];
    v.x*=inv; v.y*=inv; v.z*=inv; v.w*=inv;
    *(float4*)(g_scores + base + tid*4) = v;
}

// ---------------- layernorm --------------------------------------------------
__global__ __launch_bounds__(256) void ln_kernel(
        const float* __restrict__ a, const float* __restrict__ bsum,
        const float* __restrict__ bias,
        const float* __restrict__ g, const float* __restrict__ beta,
        float* __restrict__ out)
{
    __shared__ float red[256];
    const int t = blockIdx.x, tid = threadIdx.x;
    const float* ap = a    + (size_t)t * D_;
    const float* bp = bsum + (size_t)t * D_;
    float v[3]; float s = 0.f;
    #pragma unroll
    for (int j=0;j<3;j++) {
        int i = tid + j*256;
        float x = ap[i] + bp[i];
        if (bias) x += bias[i];
        v[j] = x; s += x;
    }
    red[tid]=s; __syncthreads();
    for (int st=128; st>0; st>>=1) { if (tid<st) red[tid]+=red[tid+st]; __syncthreads(); }
    float mu = red[0] * (1.0f/768.0f);
    __syncthreads();
    float q = 0.f;
    #pragma unroll
    for (int j=0;j<3;j++) { float d = v[j]-mu; q += d*d; }
    red[tid]=q; __syncthreads();
    for (int st=128; st>0; st>>=1) { if (tid<st) red[tid]+=red[tid+st]; __syncthreads(); }
    float inv = rsqrtf(red[0]*(1.0f/768.0f) + 1e-12f);
    #pragma unroll
    for (int j=0;j<3;j++) {
        int i = tid + j*256;
        out[(size_t)t*D_ + i] = (v[j]-mu)*inv*g[i] + beta[i];
    }
}

// ---------------- router ------------------------------------------------------
__global__ __launch_bounds__(256) void router_kernel(
        const float* __restrict__ Wr, const float* __restrict__ br)
{
    int warp = (blockIdx.x * blockDim.x + threadIdx.x) >> 5;
    int lane = threadIdx.x & 31;
    if (warp >= T_) return;
    const float* xrow = g_att + (size_t)warp * D_;
    float acc[E_];
    #pragma unroll
    for (int e=0;e<E_;e++) acc[e]=0.f;
    for (int i = lane; i < D_; i += 32) {
        float x = xrow[i];
        const float* w = Wr + i*E_;
        #pragma unroll
        for (int e=0;e<E_;e++) acc[e] += x * w[e];
    }
    #pragma unroll
    for (int e=0;e<E_;e++)
        #pragma unroll
        for (int o=16;o>0;o>>=1)
            acc[e] += __shfl_xor_sync(0xffffffffu, acc[e], o);
    if (lane == 0) {
        float best = -1e30f; int be = 0;
        #pragma unroll
        for (int e=0;e<E_;e++) {
            float l = acc[e] + br[e];
            acc[e] = l;
            if (l > best) { best = l; be = e; }
        }
        float sm = 0.f;
        #pragma unroll
        for (int e=0;e<E_;e++) sm += expf(acc[e] - best);
        float gate = 1.0f / sm;
        int pos = atomicAdd(&g_cnt[be], 1);
        if (pos < CAP_) {
            g_tokmap[be*CAP_ + pos] = warp;
            g_gate[warp] = gate;
        }
    }
}

__global__ void zero_small() {
    if (threadIdx.x < E_) g_cnt[threadIdx.x] = 0;
}
__global__ void zero_ffn_kernel() {
    size_t i = (size_t)blockIdx.x * blockDim.x + threadIdx.x;
    if (i < (size_t)T_*D_) g_ffn[i] = 0.f;
}

// ---------------- launch ------------------------------------------------------
extern "C" void kernel_launch(void* const* d_in, const int* in_sizes, int n_in,
                              void* d_out, int out_size) {
    const float* x    = (const float*)d_in[0];
    const float* mask = (const float*)d_in[1];
    const float* Wq   = (const float*)d_in[2];
    const float* bq   = (const float*)d_in[3];
    const float* Wk   = (const float*)d_in[4];
    const float* bk   = (const float*)d_in[5];
    const float* Wv   = (const float*)d_in[6];
    const float* bv   = (const float*)d_in[7];
    const float* Wo   = (const float*)d_in[8];
    const float* bo   = (const float*)d_in[9];
    const float* ln1g = (const float*)d_in[10];
    const float* ln1b = (const float*)d_in[11];
    const float* Wr   = (const float*)d_in[12];
    const float* br   = (const float*)d_in[13];
    const float* W1   = (const float*)d_in[14];
    const float* b1   = (const float*)d_in[15];
    const float* W2   = (const float*)d_in[16];
    const float* b2   = (const float*)d_in[17];
    const float* ln2g = (const float*)d_in[18];
    const float* ln2b = (const float*)d_in[19];
    float* out = (float*)d_out;

    float *p_tmp, *p_att, *p_ffn;
    cudaGetSymbolAddress((void**)&p_tmp, g_tmp);
    cudaGetSymbolAddress((void**)&p_att, g_att);
    cudaGetSymbolAddress((void**)&p_ffn, g_ffn);

    // dynamic smem per instantiation: max(2*STAGE, 128*(BN+4)*4)
    constexpr int SH_NMAJ128 = 2 * (128*36*4 + 32*136*4);   // 71680
    constexpr int SH_KMAJ128 = 2 * (128*36*4 + 128*36*4);   // 73728
    constexpr int SH_NMAJ64  = 2 * (128*36*4 + 32*72*4);    // 55296
    cudaFuncSetAttribute((const void*)tgemm<0,128,768,0,768>,   cudaFuncAttributeMaxDynamicSharedMemorySize, SH_NMAJ128);
    cudaFuncSetAttribute((const void*)tgemm<1,128,64,1,64>,     cudaFuncAttributeMaxDynamicSharedMemorySize, SH_KMAJ128);
    cudaFuncSetAttribute((const void*)tgemm<2,64,1024,0,64>,    cudaFuncAttributeMaxDynamicSharedMemorySize, SH_NMAJ64);
    cudaFuncSetAttribute((const void*)tgemm<3,128,768,0,768>,   cudaFuncAttributeMaxDynamicSharedMemorySize, SH_NMAJ128);
    cudaFuncSetAttribute((const void*)tgemm<4,128,768,0,3072>,  cudaFuncAttributeMaxDynamicSharedMemorySize, SH_NMAJ128);
    cudaFuncSetAttribute((const void*)tgemm<5,128,3072,0,768>,  cudaFuncAttributeMaxDynamicSharedMemorySize, SH_NMAJ128);

    zero_small<<<1, 32>>>();
    zero_ffn_kernel<<<(T_*D_ + 1023)/1024, 1024>>>();

    // QKV projections (weights consumed in natural [k][n] layout)
    tgemm<0,128,768,0,768><<<dim3(6,64,1), 256, SH_NMAJ128>>>(x, Wq, bq, nullptr, 0);
    tgemm<0,128,768,0,768><<<dim3(6,64,1), 256, SH_NMAJ128>>>(x, Wk, bk, nullptr, 1);
    tgemm<0,128,768,0,768><<<dim3(6,64,1), 256, SH_NMAJ128>>>(x, Wv, bv, nullptr, 2);

    // attention
    tgemm<1,128,64,1,64><<<dim3(8,8,B_*H_), 256, SH_KMAJ128>>>(nullptr, nullptr, nullptr, mask, 0);
    softmax_kernel<<<B_*H_*S_, 256>>>();
    tgemm<2,64,1024,0,64><<<dim3(1,8,B_*H_), 256, SH_NMAJ64>>>(nullptr, nullptr, nullptr, nullptr, 0);

    // att = LN1(x + ctx@Wo + bo)
    tgemm<3,128,768,0,768><<<dim3(6,64,1), 256, SH_NMAJ128>>>(nullptr, Wo, nullptr, nullptr, 0);
    ln_kernel<<<T_, 256>>>(x, p_tmp, bo, ln1g, ln1b, p_att);

    // router + MoE
    router_kernel<<<T_/8, 256>>>(Wr, br);
    tgemm<4,128,768,0,3072><<<dim3(FF_/128, (E_*CAP_)/128, 1), 256, SH_NMAJ128>>>(nullptr, W1, b1, nullptr, 0);
    tgemm<5,128,3072,0,768><<<dim3(D_/128, (E_*CAP_)/128, 1), 256, SH_NMAJ128>>>(nullptr, W2, b2, nullptr, 0);

    // out = LN2(att + ffn)
    ln_kernel<<<T_, 256>>>(p_att, p_ffn, nullptr, ln2g, ln2b, out);
}

// round 5
// speedup vs baseline: 3.8905x; 1.0230x over previous
#include <cuda_runtime.h>
#include <cstdint>
#include <math.h>

#define B_  8
#define S_  1024
#define D_  768
#define H_  12
#define DH_ 64
#define FF_ 3072
#define E_  8
#define CAP_ 2048
#define T_  8192

// ---------------- scratch (device globals) ----------------------------------
__device__ float g_q[B_*H_*S_*DH_];
__device__ float g_k[B_*H_*S_*DH_];
__device__ float g_v[B_*H_*S_*DH_];
__device__ float g_scores[100663296];      // B*H*S*S  (exp'd, tile-stabilized)
__device__ float g_ctx[T_*D_];
__device__ float g_tmp[T_*D_];
__device__ float g_att[T_*D_];
__device__ float g_h[50331648];            // E*CAP*FF
__device__ float g_ffn[T_*D_];
__device__ int   g_cnt[E_];
__device__ int   g_tokmap[E_*CAP_];
__device__ float g_gate[T_];
// per-(z,tile,row) softmax stats
__device__ float g_statM[96*8*1024];
__device__ float g_statL[96*8*1024];
__device__ float g_scale[96*8*1024];

__device__ __forceinline__ float gelu_f(float x) {
    return 0.5f * x * (1.0f + erff(x * 0.70710678118654752f));
}

__device__ __forceinline__ void cpa16(uint32_t dst, const void* src) {
    asm volatile("cp.async.ca.shared.global [%0], [%1], 16;" :: "r"(dst), "l"(src));
}
__device__ __forceinline__ void cpa_commit() {
    asm volatile("cp.async.commit_group;" ::: "memory");
}
__device__ __forceinline__ void cpa_wait0() {
    asm volatile("cp.async.wait_group 0;" ::: "memory");
}
__device__ __forceinline__ void cpa_wait1() {
    asm volatile("cp.async.wait_group 1;" ::: "memory");
}
__device__ __forceinline__ void mma8(float* c, const uint32_t* a, const uint32_t* b) {
    asm volatile(
        "mma.sync.aligned.m16n8k8.row.col.f32.tf32.tf32.f32 "
        "{%0,%1,%2,%3}, {%4,%5,%6,%7}, {%8,%9}, {%0,%1,%2,%3};\n"
        : "+f"(c[0]), "+f"(c[1]), "+f"(c[2]), "+f"(c[3])
        : "r"(a[0]), "r"(a[1]), "r"(a[2]), "r"(a[3]), "r"(b[0]), "r"(b[1]));
}

// ---------------- tf32 mma.sync GEMM -----------------------------------------
// C tile 128 x BN, 256 threads = 8 warps (2 x 4), warp tile 64 x (BN/4).
// A[M][KK] k-major (opt. row-gathered via rIdx).
// B: BKMAJ=1 -> B[n][k] k-major; BKMAJ=0 -> B[k][n] n-major (natural weights/V)
// MODE 0: QKV proj, z selects (Wq,bq)/(Wk,bk)/(Wv,bv); scatter to headed layout
// MODE 1: scores: exp(q@k^T*0.125+mask - rowtile_max); stats to g_statM/L
// MODE 2: ctx = (scaled P) @ v ; per-row-tile scale applied to A fragments
// MODE 3: ctx @ Wo -> g_tmp
// MODE 4: gather(att) @ W1[e] + b1 -> gelu -> g_h
// MODE 5: g_h @ W2[e] + b2, * gate, scatter -> g_ffn
template<int MODE, int BN, int KK, int BKMAJ, int LDBG>
__global__ __launch_bounds__(256, 2)
void tgemm(const float* __restrict__ Ag, const float* __restrict__ Bg,
           const float* __restrict__ Bg2, const float* __restrict__ Bg3,
           const float* __restrict__ bias, const float* __restrict__ bias2,
           const float* __restrict__ bias3, const float* __restrict__ mask)
{
    constexpr int NC     = KK / 32;
    constexpr int WCOLS  = BN / 4;
    constexpr int NT     = WCOLS / 8;
    constexpr int LDA    = 36;                 // floats
    constexpr int LDBK   = 36;
    constexpr int LDBN   = BN + 8;
    constexpr int ABYTES = 128 * LDA * 4;
    constexpr int BBYTES = BKMAJ ? BN * LDBK * 4 : 32 * LDBN * 4;
    constexpr int STAGE  = ABYTES + BBYTES;
    constexpr int CS     = BN + 4;
    constexpr int BF4    = BN / 4;

    extern __shared__ char smc[];
    __shared__ int rIdx[128];
    __shared__ int s_cnt;

    const int tid = threadIdx.x, wid = tid >> 5, lane = tid & 31;
    const int wr = wid >> 2, wc = wid & 3;
    const int g = lane >> 2, t = lane & 3;
    const int mBase = blockIdx.y * 128, nBase = blockIdx.x * BN, z = blockIdx.z;
    const int e = (MODE >= 4) ? (mBase >> 11) : 0;

    if (MODE == 4 || MODE == 5) {
        if (tid == 0) s_cnt = g_cnt[e];
        __syncthreads();
        if ((mBase & (CAP_-1)) >= s_cnt) return;
    }

    const float* A; const float* Bp; const float* biasp = bias;
    if      (MODE == 0) { A = Ag; Bp = (z==0)?Bg:((z==1)?Bg2:Bg3);
                          biasp = (z==0)?bias:((z==1)?bias2:bias3); }
    else if (MODE == 1) { A = g_q + (size_t)z * S_ * DH_;        Bp = g_k + (size_t)z * S_ * DH_; }
    else if (MODE == 2) { A = g_scores + (size_t)z * S_ * S_;    Bp = g_v + (size_t)z * S_ * DH_; }
    else if (MODE == 3) { A = g_ctx;                             Bp = Bg; }
    else if (MODE == 4) { A = g_att;  Bp = Bg + (size_t)e * D_ * FF_; }
    else                { A = g_h;    Bp = Bg + (size_t)e * FF_ * D_; }

    if (tid < 128) {
        int m = mBase + tid, r = m;
        if (MODE == 4) {
            int pos = m & (CAP_-1);
            r = (pos < s_cnt) ? g_tokmap[e*CAP_ + pos] : 0;
        }
        rIdx[tid] = r;
    }
    __syncthreads();

    uint32_t sU = (uint32_t)__cvta_generic_to_shared(smc);

    auto issue = [&](int cix) {
        const int stg = cix % 3;
        const int k0 = cix * 32;
        const uint32_t aB = sU + stg * STAGE;
        #pragma unroll
        for (int i = 0; i < 4; i++) {
            int idx = tid + i * 256;
            int row = idx >> 3, c4 = idx & 7;
            cpa16(aB + row * (LDA*4) + c4 * 16,
                  A + (size_t)rIdx[row] * KK + k0 + c4 * 4);
        }
        const uint32_t bB = aB + ABYTES;
        if (BKMAJ) {
            #pragma unroll
            for (int i = 0; i < BN/32; i++) {
                int idx = tid + i * 256;
                int row = idx >> 3, c4 = idx & 7;
                cpa16(bB + row * (LDBK*4) + c4 * 16,
                      Bp + (size_t)(nBase + row) * LDBG + k0 + c4 * 4);
            }
        } else {
            #pragma unroll
            for (int i = 0; i < (32*BF4)/256; i++) {
                int idx = tid + i * 256;
                int row = idx / BF4, c4 = idx % BF4;
                cpa16(bB + row * (LDBN*4) + c4 * 16,
                      Bp + (size_t)(k0 + row) * LDBG + nBase + c4 * 4);
            }
        }
        cpa_commit();
    };

    float acc[4][NT][4];
    #pragma unroll
    for (int i = 0; i < 4; i++)
        #pragma unroll
        for (int j = 0; j < NT; j++)
            #pragma unroll
            for (int q = 0; q < 4; q++) acc[i][j][q] = 0.f;

    float s0[4], s1[4];   // MODE 2 row scales (per k-tile)

    issue(0);
    if (NC > 1) issue(1);

    for (int c = 0; c < NC; c++) {
        if (MODE == 2 && (c & 3) == 0) {
            int ti = c >> 2;
            const float* sc = g_scale + ((size_t)z*8 + ti)*1024 + mBase;
            #pragma unroll
            for (int mt = 0; mt < 4; mt++) {
                int r = wr*64 + mt*16 + g;
                s0[mt] = sc[r]; s1[mt] = sc[r+8];
            }
        }
        if (c + 1 < NC) cpa_wait1(); else cpa_wait0();
        __syncthreads();
        if (c + 2 < NC) issue(c + 2);

        const int stg = c % 3;
        const uint32_t* aS = (const uint32_t*)(smc + stg * STAGE);
        const uint32_t* bS = (const uint32_t*)(smc + stg * STAGE + ABYTES);
        #pragma unroll
        for (int ks = 0; ks < 4; ks++) {
            uint32_t a[4][4];
            #pragma unroll
            for (int mt = 0; mt < 4; mt++) {
                int r = wr*64 + mt*16 + g;
                int cc = ks*8 + t;
                a[mt][0] = aS[r*LDA + cc];
                a[mt][1] = aS[(r+8)*LDA + cc];
                a[mt][2] = aS[r*LDA + cc + 4];
                a[mt][3] = aS[(r+8)*LDA + cc + 4];
                if (MODE == 2) {
                    a[mt][0] = __float_as_uint(__uint_as_float(a[mt][0]) * s0[mt]);
                    a[mt][1] = __float_as_uint(__uint_as_float(a[mt][1]) * s1[mt]);
                    a[mt][2] = __float_as_uint(__uint_as_float(a[mt][2]) * s0[mt]);
                    a[mt][3] = __float_as_uint(__uint_as_float(a[mt][3]) * s1[mt]);
                }
            }
            uint32_t b[NT][2];
            #pragma unroll
            for (int nt = 0; nt < NT; nt++) {
                int n = wc*WCOLS + nt*8 + g;
                int k = ks*8 + t;
                if (BKMAJ) {
                    b[nt][0] = bS[n*LDBK + k];
                    b[nt][1] = bS[n*LDBK + k + 4];
                } else {
                    b[nt][0] = bS[k*LDBN + n];
                    b[nt][1] = bS[(k+4)*LDBN + n];
                }
            }
            #pragma unroll
            for (int mt = 0; mt < 4; mt++)
                #pragma unroll
                for (int nt = 0; nt < NT; nt++)
                    mma8(acc[mt][nt], a[mt], b[nt]);
        }
    }
    __syncthreads();

    // ---------------- epilogue: dump accums to smem, fused stores ----------
    float* cSf = (float*)smc;
    #pragma unroll
    for (int mt = 0; mt < 4; mt++) {
        #pragma unroll
        for (int nt = 0; nt < NT; nt++) {
            int r = wr*64 + mt*16 + g;
            int n = wc*WCOLS + nt*8 + 2*t;
            *(float2*)(cSf + r*CS + n)     = make_float2(acc[mt][nt][0], acc[mt][nt][1]);
            *(float2*)(cSf + (r+8)*CS + n) = make_float2(acc[mt][nt][2], acc[mt][nt][3]);
        }
    }
    __syncthreads();

    constexpr int IT = (128 * BF4) / 256;
    #pragma unroll
    for (int it = 0; it < IT; it++) {
        int idx = it * 256 + tid;
        int row = idx / BF4, q = idx % BF4;
        float4 v = *(const float4*)(cSf + row*CS + q*4);
        int m  = mBase + row;
        int n0 = nBase + q*4;

        if (MODE == 0) {
            v.x += biasp[n0]; v.y += biasp[n0+1]; v.z += biasp[n0+2]; v.w += biasp[n0+3];
            int b = m >> 10, srow = m & 1023, hh = n0 >> 6, dh = n0 & 63;
            float* dst = (z == 0) ? g_q : ((z == 1) ? g_k : g_v);
            *(float4*)(dst + (((size_t)(b*H_ + hh)) * S_ + srow) * DH_ + dh) = v;
        } else if (MODE == 1) {
            // row is fully owned by this warp (BF4=32): warp-reduce max & sum
            int b = z / H_;
            const float4 mk = *(const float4*)(mask + b * S_ + n0);
            v = make_float4(v.x*0.125f + mk.x, v.y*0.125f + mk.y,
                            v.z*0.125f + mk.z, v.w*0.125f + mk.w);
            float mx = fmaxf(fmaxf(v.x, v.y), fmaxf(v.z, v.w));
            #pragma unroll
            for (int o = 16; o > 0; o >>= 1)
                mx = fmaxf(mx, __shfl_xor_sync(0xffffffffu, mx, o));
            float4 ev = make_float4(expf(v.x-mx), expf(v.y-mx), expf(v.z-mx), expf(v.w-mx));
            float sm = ev.x + ev.y + ev.z + ev.w;
            #pragma unroll
            for (int o = 16; o > 0; o >>= 1)
                sm += __shfl_xor_sync(0xffffffffu, sm, o);
            *(float4*)(g_scores + (size_t)z*S_*S_ + (size_t)m*S_ + n0) = ev;
            if (lane == 0) {
                size_t si = ((size_t)z*8 + blockIdx.x)*1024 + m;
                g_statM[si] = mx;
                g_statL[si] = sm;
            }
        } else if (MODE == 2) {
            int b = z / H_, hh = z % H_;
            *(float4*)(g_ctx + ((size_t)(b*S_ + m)) * D_ + hh*DH_ + n0) = v;
        } else if (MODE == 3) {
            *(float4*)(g_tmp + (size_t)m * D_ + n0) = v;
        } else if (MODE == 4) {
            int pos = m & (CAP_-1);
            if (pos < s_cnt) {
                const float4 bb = *(const float4*)(bias + (size_t)e*FF_ + n0);
                *(float4*)(g_h + (size_t)m * FF_ + n0) =
                    make_float4(gelu_f(v.x+bb.x), gelu_f(v.y+bb.y),
                                gelu_f(v.z+bb.z), gelu_f(v.w+bb.w));
            }
        } else {
            int pos = m & (CAP_-1);
            if (pos < s_cnt) {
                int tok = g_tokmap[e*CAP_ + pos];
                float gsc = g_gate[tok];
                const float4 bb = *(const float4*)(bias + (size_t)e*D_ + n0);
                *(float4*)(g_ffn + (size_t)tok * D_ + n0) =
                    make_float4((v.x+bb.x)*gsc, (v.y+bb.y)*gsc,
                                (v.z+bb.z)*gsc, (v.w+bb.w)*gsc);
            }
        }
    }
}

// ---------------- combine per-tile stats -> per-(row,tile) scales ------------
__global__ __launch_bounds__(256) void stats_kernel() {
    int idx = blockIdx.x * 256 + threadIdx.x;   // z*1024 + row
    if (idx >= 96 * 1024) return;
    int z = idx >> 10, r = idx & 1023;
    float m[8], et[8];
    float mg = -1e30f;
    #pragma unroll
    for (int ti = 0; ti < 8; ti++) {
        m[ti] = g_statM[((size_t)z*8 + ti)*1024 + r];
        mg = fmaxf(mg, m[ti]);
    }
    float lg = 0.f;
    #pragma unroll
    for (int ti = 0; ti < 8; ti++) {
        et[ti] = expf(m[ti] - mg);
        lg += g_statL[((size_t)z*8 + ti)*1024 + r] * et[ti];
    }
    float inv = 1.0f / lg;
    #pragma unroll
    for (int ti = 0; ti < 8; ti++)
        g_scale[((size_t)z*8 + ti)*1024 + r] = et[ti] * inv;
}

// ---------------- layernorm --------------------------------------------------
__global__ __launch_bounds__(256) void ln_kernel(
        const float* __restrict__ a, const float* __restrict__ bsum,
        const float* __restrict__ bias,
        const float* __restrict__ g, const float* __restrict__ beta,
        float* __restrict__ out)
{
    __shared__ float red[256];
    const int t = blockIdx.x, tid = threadIdx.x;
    const float* ap = a    + (size_t)t * D_;
    const float* bp = bsum + (size_t)t * D_;
    float v[3]; float s = 0.f;
    #pragma unroll
    for (int j=0;j<3;j++) {
        int i = tid + j*256;
        float x = ap[i] + bp[i];
        if (bias) x += bias[i];
        v[j] = x; s += x;
    }
    red[tid]=s; __syncthreads();
    for (int st=128; st>0; st>>=1) { if (tid<st) red[tid]+=red[tid+st]; __syncthreads(); }
    float mu = red[0] * (1.0f/768.0f);
    __syncthreads();
    float q = 0.f;
    #pragma unroll
    for (int j=0;j<3;j++) { float d = v[j]-mu; q += d*d; }
    red[tid]=q; __syncthreads();
    for (int st=128; st>0; st>>=1) { if (tid<st) red[tid]+=red[tid+st]; __syncthreads(); }
    float inv = rsqrtf(red[0]*(1.0f/768.0f) + 1e-12f);
    #pragma unroll
    for (int j=0;j<3;j++) {
        int i = tid + j*256;
        out[(size_t)t*D_ + i] = (v[j]-mu)*inv*g[i] + beta[i];
    }
}

// ---------------- router ------------------------------------------------------
__global__ __launch_bounds__(256) void router_kernel(
        const float* __restrict__ Wr, const float* __restrict__ br)
{
    int warp = (blockIdx.x * blockDim.x + threadIdx.x) >> 5;
    int lane = threadIdx.x & 31;
    if (warp >= T_) return;
    const float* xrow = g_att + (size_t)warp * D_;
    float acc[E_];
    #pragma unroll
    for (int e=0;e<E_;e++) acc[e]=0.f;
    for (int i = lane; i < D_; i += 32) {
        float x = xrow[i];
        const float* w = Wr + i*E_;
        #pragma unroll
        for (int e=0;e<E_;e++) acc[e] += x * w[e];
    }
    #pragma unroll
    for (int e=0;e<E_;e++)
        #pragma unroll
        for (int o=16;o>0;o>>=1)
            acc[e] += __shfl_xor_sync(0xffffffffu, acc[e], o);
    if (lane == 0) {
        float best = -1e30f; int be = 0;
        #pragma unroll
        for (int e=0;e<E_;e++) {
            float l = acc[e] + br[e];
            acc[e] = l;
            if (l > best) { best = l; be = e; }
        }
        float sm = 0.f;
        #pragma unroll
        for (int e=0;e<E_;e++) sm += expf(acc[e] - best);
        float gate = 1.0f / sm;
        int pos = atomicAdd(&g_cnt[be], 1);
        if (pos < CAP_) {
            g_tokmap[be*CAP_ + pos] = warp;
            g_gate[warp] = gate;
        }
    }
}

__global__ void zero_small() {
    if (threadIdx.x < E_) g_cnt[threadIdx.x] = 0;
}
__global__ void zero_ffn_kernel() {
    size_t i = (size_t)blockIdx.x * blockDim.x + threadIdx.x;
    if (i < (size_t)T_*D_) g_ffn[i] = 0.f;
}

// ---------------- launch ------------------------------------------------------
extern "C" void kernel_launch(void* const* d_in, const int* in_sizes, int n_in,
                              void* d_out, int out_size) {
    const float* x    = (const float*)d_in[0];
    const float* mask = (const float*)d_in[1];
    const float* Wq   = (const float*)d_in[2];
    const float* bq   = (const float*)d_in[3];
    const float* Wk   = (const float*)d_in[4];
    const float* bk   = (const float*)d_in[5];
    const float* Wv   = (const float*)d_in[6];
    const float* bv   = (const float*)d_in[7];
    const float* Wo   = (const float*)d_in[8];
    const float* bo   = (const float*)d_in[9];
    const float* ln1g = (const float*)d_in[10];
    const float* ln1b = (const float*)d_in[11];
    const float* Wr   = (const float*)d_in[12];
    const float* br   = (const float*)d_in[13];
    const float* W1   = (const float*)d_in[14];
    const float* b1   = (const float*)d_in[15];
    const float* W2   = (const float*)d_in[16];
    const float* b2   = (const float*)d_in[17];
    const float* ln2g = (const float*)d_in[18];
    const float* ln2b = (const float*)d_in[19];
    float* out = (float*)d_out;

    float *p_tmp, *p_att, *p_ffn;
    cudaGetSymbolAddress((void**)&p_tmp, g_tmp);
    cudaGetSymbolAddress((void**)&p_att, g_att);
    cudaGetSymbolAddress((void**)&p_ffn, g_ffn);

    // dynamic smem: max(3*STAGE, epilogue 128*(BN+4)*4)
    constexpr int SH_NMAJ128 = 3 * (128*36*4 + 32*136*4);   // 107520
    constexpr int SH_KMAJ128 = 3 * (128*36*4 + 128*36*4);   // 110592
    constexpr int SH_NMAJ64  = 3 * (128*36*4 + 32*72*4);    // 82944
    cudaFuncSetAttribute((const void*)tgemm<0,128,768,0,768>,   cudaFuncAttributeMaxDynamicSharedMemorySize, SH_NMAJ128);
    cudaFuncSetAttribute((const void*)tgemm<1,128,64,1,64>,     cudaFuncAttributeMaxDynamicSharedMemorySize, SH_KMAJ128);
    cudaFuncSetAttribute((const void*)tgemm<2,64,1024,0,64>,    cudaFuncAttributeMaxDynamicSharedMemorySize, SH_NMAJ64);
    cudaFuncSetAttribute((const void*)tgemm<3,128,768,0,768>,   cudaFuncAttributeMaxDynamicSharedMemorySize, SH_NMAJ128);
    cudaFuncSetAttribute((const void*)tgemm<4,128,768,0,3072>,  cudaFuncAttributeMaxDynamicSharedMemorySize, SH_NMAJ128);
    cudaFuncSetAttribute((const void*)tgemm<5,128,3072,0,768>,  cudaFuncAttributeMaxDynamicSharedMemorySize, SH_NMAJ128);

    zero_small<<<1, 32>>>();
    zero_ffn_kernel<<<(T_*D_ + 1023)/1024, 1024>>>();

    // fused QKV projections (one launch, z selects weight/bias)
    tgemm<0,128,768,0,768><<<dim3(6,64,3), 256, SH_NMAJ128>>>(x, Wq, Wk, Wv, bq, bk, bv, nullptr);

    // attention: scores(+exp+stats) -> combine -> ctx (scaled A)
    tgemm<1,128,64,1,64><<<dim3(8,8,B_*H_), 256, SH_KMAJ128>>>(nullptr, nullptr, nullptr, nullptr, nullptr, nullptr, nullptr, mask);
    stats_kernel<<<(96*1024 + 255)/256, 256>>>();
    tgemm<2,64,1024,0,64><<<dim3(1,8,B_*H_), 256, SH_NMAJ64>>>(nullptr, nullptr, nullptr, nullptr, nullptr, nullptr, nullptr, nullptr);

    // att = LN1(x + ctx@Wo + bo)
    tgemm<3,128,768,0,768><<<dim3(6,64,1), 256, SH_NMAJ128>>>(nullptr, Wo, nullptr, nullptr, nullptr, nullptr, nullptr, nullptr);
    ln_kernel<<<T_, 256>>>(x, p_tmp, bo, ln1g, ln1b, p_att);

    // router + MoE
    router_kernel<<<T_/8, 256>>>(Wr, br);
    tgemm<4,128,768,0,3072><<<dim3(FF_/128, (E_*CAP_)/128, 1), 256, SH_NMAJ128>>>(nullptr, W1, nullptr, nullptr, b1, nullptr, nullptr, nullptr);
    tgemm<5,128,3072,0,768><<<dim3(D_/128, (E_*CAP_)/128, 1), 256, SH_NMAJ128>>>(nullptr, W2, nullptr, nullptr, b2, nullptr, nullptr, nullptr);

    // out = LN2(att + ffn)
    ln_kernel<<<T_, 256>>>(p_att, p_ffn, nullptr, ln2g, ln2b, out);
}

// round 6
// speedup vs baseline: 4.3192x; 1.1102x over previous
#include <cuda_runtime.h>
#include <cstdint>
#include <math.h>

#define B_  8
#define S_  1024
#define D_  768
#define H_  12
#define DH_ 64
#define FF_ 3072
#define E_  8
#define CAP_ 2048
#define T_  8192

// ---------------- scratch (device globals) ----------------------------------
__device__ float g_q[B_*H_*S_*DH_];
__device__ float g_k[B_*H_*S_*DH_];
__device__ float g_v[B_*H_*S_*DH_];
__device__ float g_ctx[T_*D_];
__device__ float g_tmp[T_*D_];
__device__ float g_att[T_*D_];
__device__ float g_h[50331648];            // E*CAP*FF
__device__ float g_ffn[T_*D_];
__device__ int   g_cnt[E_];
__device__ int   g_tokmap[E_*CAP_];
__device__ float g_gate[T_];

__device__ __forceinline__ float gelu_f(float x) {
    return 0.5f * x * (1.0f + erff(x * 0.70710678118654752f));
}

__device__ __forceinline__ void cpa16(uint32_t dst, const void* src) {
    asm volatile("cp.async.ca.shared.global [%0], [%1], 16;" :: "r"(dst), "l"(src));
}
__device__ __forceinline__ void cpa_commit() {
    asm volatile("cp.async.commit_group;" ::: "memory");
}
__device__ __forceinline__ void cpa_wait0() {
    asm volatile("cp.async.wait_group 0;" ::: "memory");
}
__device__ __forceinline__ void cpa_wait1() {
    asm volatile("cp.async.wait_group 1;" ::: "memory");
}
__device__ __forceinline__ void mma8(float* c, const uint32_t* a, const uint32_t* b) {
    asm volatile(
        "mma.sync.aligned.m16n8k8.row.col.f32.tf32.tf32.f32 "
        "{%0,%1,%2,%3}, {%4,%5,%6,%7}, {%8,%9}, {%0,%1,%2,%3};\n"
        : "+f"(c[0]), "+f"(c[1]), "+f"(c[2]), "+f"(c[3])
        : "r"(a[0]), "r"(a[1]), "r"(a[2]), "r"(a[3]), "r"(b[0]), "r"(b[1]));
}

// ================= fused flash attention =====================================
// grid (8 mtiles, 96 z), 256 threads. Each warp owns 16 Q rows.
// Streams K/V in 64-key tiles (double-buffered cp.async), online softmax,
// accumulates O in registers, writes g_ctx (headed layout).
__global__ __launch_bounds__(256) void fattn(const float* __restrict__ mask)
{
    constexpr int LDK = 68, LDV = 72, LDP = 68;
    constexpr int KBYTES = 64 * LDK * 4;     // 17408
    constexpr int VBYTES = 64 * LDV * 4;     // 18432
    constexpr int MBYTES = 256;              // 64-float mask slice
    constexpr int STAGE  = KBYTES + VBYTES + MBYTES;
    extern __shared__ char smc[];
    float* pS_all = (float*)(smc + 2 * STAGE);

    const int tid = threadIdx.x, wid = tid >> 5, lane = tid & 31;
    const int g = lane >> 2, t = lane & 3;
    const int z = blockIdx.y, mBase = blockIdx.x * 128;
    const int bq = z / H_, hh = z % H_;
    const int m0 = mBase + wid * 16;

    const float* Qp = g_q + (size_t)z * S_ * DH_;
    const float* Kp = g_k + (size_t)z * S_ * DH_;
    const float* Vp = g_v + (size_t)z * S_ * DH_;

    // Q fragments (one-time gmem loads)
    uint32_t qf[8][4];
    #pragma unroll
    for (int kb = 0; kb < 8; kb++) {
        qf[kb][0] = __float_as_uint(Qp[(m0 + g)     * DH_ + kb*8 + t]);
        qf[kb][1] = __float_as_uint(Qp[(m0 + g + 8) * DH_ + kb*8 + t]);
        qf[kb][2] = __float_as_uint(Qp[(m0 + g)     * DH_ + kb*8 + t + 4]);
        qf[kb][3] = __float_as_uint(Qp[(m0 + g + 8) * DH_ + kb*8 + t + 4]);
    }

    float oacc[8][4];
    #pragma unroll
    for (int nt = 0; nt < 8; nt++)
        #pragma unroll
        for (int q = 0; q < 4; q++) oacc[nt][q] = 0.f;
    float mrow0 = -1e30f, mrow1 = -1e30f, lrow0 = 0.f, lrow1 = 0.f;

    uint32_t sU = (uint32_t)__cvta_generic_to_shared(smc);
    auto issue = [&](int kt) {
        const int stg = kt & 1;
        const uint32_t base = sU + stg * STAGE;
        #pragma unroll
        for (int i = 0; i < 4; i++) {
            int idx = tid + i * 256;
            int row = idx >> 4, c4 = idx & 15;
            cpa16(base + row * (LDK*4) + c4 * 16,
                  Kp + (size_t)(kt*64 + row) * DH_ + c4 * 4);
        }
        #pragma unroll
        for (int i = 0; i < 4; i++) {
            int idx = tid + i * 256;
            int row = idx >> 4, c4 = idx & 15;
            cpa16(base + KBYTES + row * (LDV*4) + c4 * 16,
                  Vp + (size_t)(kt*64 + row) * DH_ + c4 * 4);
        }
        if (tid < 16)
            cpa16(base + KBYTES + VBYTES + tid * 16, mask + bq * S_ + kt*64 + tid * 4);
        cpa_commit();
    };

    float* pS = pS_all + wid * 16 * LDP;

    issue(0);
    for (int kt = 0; kt < 16; kt++) {
        cpa_wait0();
        __syncthreads();
        if (kt + 1 < 16) issue(kt + 1);

        const int stg = kt & 1;
        const float* kS = (const float*)(smc + stg * STAGE);
        const float* vS = (const float*)(smc + stg * STAGE + KBYTES);
        const float* mS = (const float*)(smc + stg * STAGE + KBYTES + VBYTES);

        // ---- scores strip 16 x 64 ----
        float sacc[8][4];
        #pragma unroll
        for (int nt = 0; nt < 8; nt++)
            #pragma unroll
            for (int q = 0; q < 4; q++) sacc[nt][q] = 0.f;
        #pragma unroll
        for (int ks = 0; ks < 8; ks++) {
            #pragma unroll
            for (int nt = 0; nt < 8; nt++) {
                uint32_t b[2];
                b[0] = __float_as_uint(kS[(nt*8 + g) * LDK + ks*8 + t]);
                b[1] = __float_as_uint(kS[(nt*8 + g) * LDK + ks*8 + t + 4]);
                mma8(sacc[nt], qf[ks], b);
            }
        }

        // ---- scale + mask + row max ----
        float mx0 = -1e30f, mx1 = -1e30f;
        #pragma unroll
        for (int nt = 0; nt < 8; nt++) {
            float mk0 = mS[nt*8 + 2*t], mk1 = mS[nt*8 + 2*t + 1];
            sacc[nt][0] = sacc[nt][0]*0.125f + mk0;
            sacc[nt][1] = sacc[nt][1]*0.125f + mk1;
            sacc[nt][2] = sacc[nt][2]*0.125f + mk0;
            sacc[nt][3] = sacc[nt][3]*0.125f + mk1;
            mx0 = fmaxf(mx0, fmaxf(sacc[nt][0], sacc[nt][1]));
            mx1 = fmaxf(mx1, fmaxf(sacc[nt][2], sacc[nt][3]));
        }
        mx0 = fmaxf(mx0, __shfl_xor_sync(0xffffffffu, mx0, 1));
        mx0 = fmaxf(mx0, __shfl_xor_sync(0xffffffffu, mx0, 2));
        mx1 = fmaxf(mx1, __shfl_xor_sync(0xffffffffu, mx1, 1));
        mx1 = fmaxf(mx1, __shfl_xor_sync(0xffffffffu, mx1, 2));

        float mn0 = fmaxf(mrow0, mx0), mn1 = fmaxf(mrow1, mx1);
        float a0 = __expf(mrow0 - mn0), a1 = __expf(mrow1 - mn1);
        mrow0 = mn0; mrow1 = mn1;

        // ---- exp, stage P (warp-private smem), partial sums ----
        float s0 = 0.f, s1 = 0.f;
        #pragma unroll
        for (int nt = 0; nt < 8; nt++) {
            float p0 = __expf(sacc[nt][0] - mn0);
            float p1 = __expf(sacc[nt][1] - mn0);
            float p2 = __expf(sacc[nt][2] - mn1);
            float p3 = __expf(sacc[nt][3] - mn1);
            s0 += p0 + p1; s1 += p2 + p3;
            *(float2*)(pS + g * LDP + nt*8 + 2*t)       = make_float2(p0, p1);
            *(float2*)(pS + (g + 8) * LDP + nt*8 + 2*t) = make_float2(p2, p3);
        }
        s0 += __shfl_xor_sync(0xffffffffu, s0, 1);
        s0 += __shfl_xor_sync(0xffffffffu, s0, 2);
        s1 += __shfl_xor_sync(0xffffffffu, s1, 1);
        s1 += __shfl_xor_sync(0xffffffffu, s1, 2);
        lrow0 = lrow0 * a0 + s0;
        lrow1 = lrow1 * a1 + s1;

        // ---- rescale O ----
        #pragma unroll
        for (int nt = 0; nt < 8; nt++) {
            oacc[nt][0] *= a0; oacc[nt][1] *= a0;
            oacc[nt][2] *= a1; oacc[nt][3] *= a1;
        }
        __syncwarp();

        // ---- P @ V (K = 64) ----
        #pragma unroll
        for (int kb = 0; kb < 8; kb++) {
            uint32_t a[4];
            a[0] = __float_as_uint(pS[g * LDP + kb*8 + t]);
            a[1] = __float_as_uint(pS[(g + 8) * LDP + kb*8 + t]);
            a[2] = __float_as_uint(pS[g * LDP + kb*8 + t + 4]);
            a[3] = __float_as_uint(pS[(g + 8) * LDP + kb*8 + t + 4]);
            #pragma unroll
            for (int nt = 0; nt < 8; nt++) {
                uint32_t b[2];
                b[0] = __float_as_uint(vS[(kb*8 + t)     * LDV + nt*8 + g]);
                b[1] = __float_as_uint(vS[(kb*8 + t + 4) * LDV + nt*8 + g]);
                mma8(oacc[nt], a, b);
            }
        }
    }

    // ---- finalize: O/l, write ctx in [B,S,H,DH] (flattened [T,D]) ----
    float inv0 = 1.0f / lrow0, inv1 = 1.0f / lrow1;
    int mr0 = m0 + g, mr1 = m0 + g + 8;
    #pragma unroll
    for (int nt = 0; nt < 8; nt++) {
        int col = hh * DH_ + nt*8 + 2*t;
        *(float2*)(g_ctx + ((size_t)(bq * S_ + mr0)) * D_ + col) =
            make_float2(oacc[nt][0] * inv0, oacc[nt][1] * inv0);
        *(float2*)(g_ctx + ((size_t)(bq * S_ + mr1)) * D_ + col) =
            make_float2(oacc[nt][2] * inv1, oacc[nt][3] * inv1);
    }
}

// ---------------- tf32 mma.sync GEMM -----------------------------------------
// MODE 0: QKV proj, z selects (Wq,bq)/(Wk,bk)/(Wv,bv); scatter to headed layout
// MODE 3: ctx @ Wo -> g_tmp
// MODE 4: gather(att) @ W1[e] + b1 -> gelu -> g_h
// MODE 5: g_h @ W2[e] + b2, * gate, scatter -> g_ffn
template<int MODE, int BN, int KK, int BKMAJ, int LDBG>
__global__ __launch_bounds__(256, 2)
void tgemm(const float* __restrict__ Ag, const float* __restrict__ Bg,
           const float* __restrict__ Bg2, const float* __restrict__ Bg3,
           const float* __restrict__ bias, const float* __restrict__ bias2,
           const float* __restrict__ bias3)
{
    constexpr int NC     = KK / 32;
    constexpr int WCOLS  = BN / 4;
    constexpr int NT     = WCOLS / 8;
    constexpr int LDA    = 36;
    constexpr int LDBK   = 36;
    constexpr int LDBN   = BN + 8;
    constexpr int ABYTES = 128 * LDA * 4;
    constexpr int BBYTES = BKMAJ ? BN * LDBK * 4 : 32 * LDBN * 4;
    constexpr int STAGE  = ABYTES + BBYTES;
    constexpr int CS     = BN + 4;
    constexpr int BF4    = BN / 4;

    extern __shared__ char smc[];
    __shared__ int rIdx[128];
    __shared__ int s_cnt;

    const int tid = threadIdx.x, wid = tid >> 5, lane = tid & 31;
    const int wr = wid >> 2, wc = wid & 3;
    const int g = lane >> 2, t = lane & 3;
    const int mBase = blockIdx.y * 128, nBase = blockIdx.x * BN, z = blockIdx.z;
    const int e = (MODE >= 4) ? (mBase >> 11) : 0;

    if (MODE == 4 || MODE == 5) {
        if (tid == 0) s_cnt = g_cnt[e];
        __syncthreads();
        if ((mBase & (CAP_-1)) >= s_cnt) return;
    }

    const float* A; const float* Bp; const float* biasp = bias;
    if      (MODE == 0) { A = Ag; Bp = (z==0)?Bg:((z==1)?Bg2:Bg3);
                          biasp = (z==0)?bias:((z==1)?bias2:bias3); }
    else if (MODE == 3) { A = g_ctx;  Bp = Bg; }
    else if (MODE == 4) { A = g_att;  Bp = Bg + (size_t)e * D_ * FF_; }
    else                { A = g_h;    Bp = Bg + (size_t)e * FF_ * D_; }

    if (tid < 128) {
        int m = mBase + tid, r = m;
        if (MODE == 4) {
            int pos = m & (CAP_-1);
            r = (pos < s_cnt) ? g_tokmap[e*CAP_ + pos] : 0;
        }
        rIdx[tid] = r;
    }
    __syncthreads();

    uint32_t sU = (uint32_t)__cvta_generic_to_shared(smc);

    auto issue = [&](int cix) {
        const int stg = cix % 3;
        const int k0 = cix * 32;
        const uint32_t aB = sU + stg * STAGE;
        #pragma unroll
        for (int i = 0; i < 4; i++) {
            int idx = tid + i * 256;
            int row = idx >> 3, c4 = idx & 7;
            cpa16(aB + row * (LDA*4) + c4 * 16,
                  A + (size_t)rIdx[row] * KK + k0 + c4 * 4);
        }
        const uint32_t bB = aB + ABYTES;
        if (BKMAJ) {
            #pragma unroll
            for (int i = 0; i < BN/32; i++) {
                int idx = tid + i * 256;
                int row = idx >> 3, c4 = idx & 7;
                cpa16(bB + row * (LDBK*4) + c4 * 16,
                      Bp + (size_t)(nBase + row) * LDBG + k0 + c4 * 4);
            }
        } else {
            #pragma unroll
            for (int i = 0; i < (32*BF4)/256; i++) {
                int idx = tid + i * 256;
                int row = idx / BF4, c4 = idx % BF4;
                cpa16(bB + row * (LDBN*4) + c4 * 16,
                      Bp + (size_t)(k0 + row) * LDBG + nBase + c4 * 4);
            }
        }
        cpa_commit();
    };

    float acc[4][NT][4];
    #pragma unroll
    for (int i = 0; i < 4; i++)
        #pragma unroll
        for (int j = 0; j < NT; j++)
            #pragma unroll
            for (int q = 0; q < 4; q++) acc[i][j][q] = 0.f;

    issue(0);
    if (NC > 1) issue(1);

    for (int c = 0; c < NC; c++) {
        if (c + 1 < NC) cpa_wait1(); else cpa_wait0();
        __syncthreads();
        if (c + 2 < NC) issue(c + 2);

        const int stg = c % 3;
        const uint32_t* aS = (const uint32_t*)(smc + stg * STAGE);
        const uint32_t* bS = (const uint32_t*)(smc + stg * STAGE + ABYTES);
        #pragma unroll
        for (int ks = 0; ks < 4; ks++) {
            uint32_t a[4][4];
            #pragma unroll
            for (int mt = 0; mt < 4; mt++) {
                int r = wr*64 + mt*16 + g;
                int cc = ks*8 + t;
                a[mt][0] = aS[r*LDA + cc];
                a[mt][1] = aS[(r+8)*LDA + cc];
                a[mt][2] = aS[r*LDA + cc + 4];
                a[mt][3] = aS[(r+8)*LDA + cc + 4];
            }
            uint32_t b[NT][2];
            #pragma unroll
            for (int nt = 0; nt < NT; nt++) {
                int n = wc*WCOLS + nt*8 + g;
                int k = ks*8 + t;
                if (BKMAJ) {
                    b[nt][0] = bS[n*LDBK + k];
                    b[nt][1] = bS[n*LDBK + k + 4];
                } else {
                    b[nt][0] = bS[k*LDBN + n];
                    b[nt][1] = bS[(k+4)*LDBN + n];
                }
            }
            #pragma unroll
            for (int mt = 0; mt < 4; mt++)
                #pragma unroll
                for (int nt = 0; nt < NT; nt++)
                    mma8(acc[mt][nt], a[mt], b[nt]);
        }
    }
    __syncthreads();

    // ---------------- epilogue ----------------
    float* cSf = (float*)smc;
    #pragma unroll
    for (int mt = 0; mt < 4; mt++) {
        #pragma unroll
        for (int nt = 0; nt < NT; nt++) {
            int r = wr*64 + mt*16 + g;
            int n = wc*WCOLS + nt*8 + 2*t;
            *(float2*)(cSf + r*CS + n)     = make_float2(acc[mt][nt][0], acc[mt][nt][1]);
            *(float2*)(cSf + (r+8)*CS + n) = make_float2(acc[mt][nt][2], acc[mt][nt][3]);
        }
    }
    __syncthreads();

    constexpr int IT = (128 * BF4) / 256;
    #pragma unroll
    for (int it = 0; it < IT; it++) {
        int idx = it * 256 + tid;
        int row = idx / BF4, q = idx % BF4;
        float4 v = *(const float4*)(cSf + row*CS + q*4);
        int m  = mBase + row;
        int n0 = nBase + q*4;

        if (MODE == 0) {
            v.x += biasp[n0]; v.y += biasp[n0+1]; v.z += biasp[n0+2]; v.w += biasp[n0+3];
            int b = m >> 10, srow = m & 1023, hh = n0 >> 6, dh = n0 & 63;
            float* dst = (z == 0) ? g_q : ((z == 1) ? g_k : g_v);
            *(float4*)(dst + (((size_t)(b*H_ + hh)) * S_ + srow) * DH_ + dh) = v;
        } else if (MODE == 3) {
            *(float4*)(g_tmp + (size_t)m * D_ + n0) = v;
        } else if (MODE == 4) {
            int pos = m & (CAP_-1);
            if (pos < s_cnt) {
                const float4 bb = *(const float4*)(bias + (size_t)e*FF_ + n0);
                *(float4*)(g_h + (size_t)m * FF_ + n0) =
                    make_float4(gelu_f(v.x+bb.x), gelu_f(v.y+bb.y),
                                gelu_f(v.z+bb.z), gelu_f(v.w+bb.w));
            }
        } else {
            int pos = m & (CAP_-1);
            if (pos < s_cnt) {
                int tok = g_tokmap[e*CAP_ + pos];
                float gsc = g_gate[tok];
                const float4 bb = *(const float4*)(bias + (size_t)e*D_ + n0);
                *(float4*)(g_ffn + (size_t)tok * D_ + n0) =
                    make_float4((v.x+bb.x)*gsc, (v.y+bb.y)*gsc,
                                (v.z+bb.z)*gsc, (v.w+bb.w)*gsc);
            }
        }
    }
}

// ---------------- layernorm --------------------------------------------------
__global__ __launch_bounds__(256) void ln_kernel(
        const float* __restrict__ a, const float* __restrict__ bsum,
        const float* __restrict__ bias,
        const float* __restrict__ g, const float* __restrict__ beta,
        float* __restrict__ out)
{
    __shared__ float red[256];
    const int t = blockIdx.x, tid = threadIdx.x;
    const float* ap = a    + (size_t)t * D_;
    const float* bp = bsum + (size_t)t * D_;
    float v[3]; float s = 0.f;
    #pragma unroll
    for (int j=0;j<3;j++) {
        int i = tid + j*256;
        float x = ap[i] + bp[i];
        if (bias) x += bias[i];
        v[j] = x; s += x;
    }
    red[tid]=s; __syncthreads();
    for (int st=128; st>0; st>>=1) { if (tid<st) red[tid]+=red[tid+st]; __syncthreads(); }
    float mu = red[0] * (1.0f/768.0f);
    __syncthreads();
    float q = 0.f;
    #pragma unroll
    for (int j=0;j<3;j++) { float d = v[j]-mu; q += d*d; }
    red[tid]=q; __syncthreads();
    for (int st=128; st>0; st>>=1) { if (tid<st) red[tid]+=red[tid+st]; __syncthreads(); }
    float inv = rsqrtf(red[0]*(1.0f/768.0f) + 1e-12f);
    #pragma unroll
    for (int j=0;j<3;j++) {
        int i = tid + j*256;
        out[(size_t)t*D_ + i] = (v[j]-mu)*inv*g[i] + beta[i];
    }
}

// ---------------- router ------------------------------------------------------
__global__ __launch_bounds__(256) void router_kernel(
        const float* __restrict__ Wr, const float* __restrict__ br)
{
    int warp = (blockIdx.x * blockDim.x + threadIdx.x) >> 5;
    int lane = threadIdx.x & 31;
    if (warp >= T_) return;
    const float* xrow = g_att + (size_t)warp * D_;
    float acc[E_];
    #pragma unroll
    for (int e=0;e<E_;e++) acc[e]=0.f;
    for (int i = lane; i < D_; i += 32) {
        float x = xrow[i];
        const float* w = Wr + i*E_;
        #pragma unroll
        for (int e=0;e<E_;e++) acc[e] += x * w[e];
    }
    #pragma unroll
    for (int e=0;e<E_;e++)
        #pragma unroll
        for (int o=16;o>0;o>>=1)
            acc[e] += __shfl_xor_sync(0xffffffffu, acc[e], o);
    if (lane == 0) {
        float best = -1e30f; int be = 0;
        #pragma unroll
        for (int e=0;e<E_;e++) {
            float l = acc[e] + br[e];
            acc[e] = l;
            if (l > best) { best = l; be = e; }
        }
        float sm = 0.f;
        #pragma unroll
        for (int e=0;e<E_;e++) sm += expf(acc[e] - best);
        float gate = 1.0f / sm;
        int pos = atomicAdd(&g_cnt[be], 1);
        if (pos < CAP_) {
            g_tokmap[be*CAP_ + pos] = warp;
            g_gate[warp] = gate;
        }
    }
}

__global__ void zero_small() {
    if (threadIdx.x < E_) g_cnt[threadIdx.x] = 0;
}

// ---------------- launch ------------------------------------------------------
extern "C" void kernel_launch(void* const* d_in, const int* in_sizes, int n_in,
                              void* d_out, int out_size) {
    const float* x    = (const float*)d_in[0];
    const float* mask = (const float*)d_in[1];
    const float* Wq   = (const float*)d_in[2];
    const float* bq   = (const float*)d_in[3];
    const float* Wk   = (const float*)d_in[4];
    const float* bk   = (const float*)d_in[5];
    const float* Wv   = (const float*)d_in[6];
    const float* bv   = (const float*)d_in[7];
    const float* Wo   = (const float*)d_in[8];
    const float* bo   = (const float*)d_in[9];
    const float* ln1g = (const float*)d_in[10];
    const float* ln1b = (const float*)d_in[11];
    const float* Wr   = (const float*)d_in[12];
    const float* br   = (const float*)d_in[13];
    const float* W1   = (const float*)d_in[14];
    const float* b1   = (const float*)d_in[15];
    const float* W2   = (const float*)d_in[16];
    const float* b2   = (const float*)d_in[17];
    const float* ln2g = (const float*)d_in[18];
    const float* ln2b = (const float*)d_in[19];
    float* out = (float*)d_out;

    float *p_tmp, *p_att, *p_ffn;
    cudaGetSymbolAddress((void**)&p_tmp, g_tmp);
    cudaGetSymbolAddress((void**)&p_att, g_att);
    cudaGetSymbolAddress((void**)&p_ffn, g_ffn);

    constexpr int SH_NMAJ128 = 3 * (128*36*4 + 32*136*4);   // 107520
    constexpr int SH_FA      = 2 * (64*68*4 + 64*72*4 + 256) + 8*16*68*4;  // 106880
    cudaFuncSetAttribute((const void*)tgemm<0,128,768,0,768>,   cudaFuncAttributeMaxDynamicSharedMemorySize, SH_NMAJ128);
    cudaFuncSetAttribute((const void*)tgemm<3,128,768,0,768>,   cudaFuncAttributeMaxDynamicSharedMemorySize, SH_NMAJ128);
    cudaFuncSetAttribute((const void*)tgemm<4,128,768,0,3072>,  cudaFuncAttributeMaxDynamicSharedMemorySize, SH_NMAJ128);
    cudaFuncSetAttribute((const void*)tgemm<5,128,3072,0,768>,  cudaFuncAttributeMaxDynamicSharedMemorySize, SH_NMAJ128);
    cudaFuncSetAttribute((const void*)fattn, cudaFuncAttributeMaxDynamicSharedMemorySize, SH_FA);

    zero_small<<<1, 32>>>();

    // fused QKV projections
    tgemm<0,128,768,0,768><<<dim3(6,64,3), 256, SH_NMAJ128>>>(x, Wq, Wk, Wv, bq, bk, bv);

    // fused flash attention -> g_ctx
    fattn<<<dim3(8, 96), 256, SH_FA>>>(mask);

    // att = LN1(x + ctx@Wo + bo)
    tgemm<3,128,768,0,768><<<dim3(6,64,1), 256, SH_NMAJ128>>>(nullptr, Wo, nullptr, nullptr, nullptr, nullptr, nullptr);
    ln_kernel<<<T_, 256>>>(x, p_tmp, bo, ln1g, ln1b, p_att);

    // router + MoE
    router_kernel<<<T_/8, 256>>>(Wr, br);
    tgemm<4,128,768,0,3072><<<dim3(FF_/128, (E_*CAP_)/128, 1), 256, SH_NMAJ128>>>(nullptr, W1, nullptr, nullptr, b1, nullptr, nullptr);
    tgemm<5,128,3072,0,768><<<dim3(D_/128, (E_*CAP_)/128, 1), 256, SH_NMAJ128>>>(nullptr, W2, nullptr, nullptr, b2, nullptr, nullptr);

    // out = LN2(att + ffn)
    ln_kernel<<<T_, 256>>>(p_att, p_ffn, nullptr, ln2g, ln2b, out);
}